// round 12
// baseline (speedup 1.0000x reference)
#include <cuda_runtime.h>
#include <cuda_bf16.h>
#include <cstdint>

// ---------------------------------------------------------------------------
// TSAKT: gather -> ReLU MLP -> 2x causal MHA -> output proj.
// glo/ts biases are key-constant pre-mask => softmax-shift-invariant => dropped.
// R12: merge MLP+Q1+Q2 into one z-dispatched launch (they share inputs);
//      single 8-slice transpose launch. Arithmetic identical to R11.
// ---------------------------------------------------------------------------

#define Bsz 32
#define SEQ 512
#define EMB 512
#define NH  8
#define DHD 64
#define TOT (Bsz * SEQ)
#define ATTN_SCALE 0.125f

// ---- device scratch ---------------------------------------------------------
__device__ float g_outb [(size_t)TOT * EMB];
__device__ __nv_bfloat16 g_W[2 * 512 * 1024 + 12 * 512 * 512];
__device__ __nv_bfloat16 g_Hh[(size_t)TOT * 512],  g_Hl[(size_t)TOT * 512];
__device__ __nv_bfloat16 g_QRh[(size_t)TOT * EMB], g_QRl[(size_t)TOT * EMB];
__device__ __nv_bfloat16 g_Xh[(size_t)TOT * EMB],  g_Xl[(size_t)TOT * EMB];
__device__ __nv_bfloat16 g_Oh[(size_t)TOT * EMB],  g_Ol[(size_t)TOT * EMB];
__device__ __nv_bfloat16 g_Q1h[(size_t)TOT * EMB], g_Q1l[(size_t)TOT * EMB];
__device__ __nv_bfloat16 g_Q2h[(size_t)TOT * EMB], g_Q2l[(size_t)TOT * EMB];
__device__ __nv_bfloat16 g_Kh[(size_t)TOT * EMB],  g_Kl[(size_t)TOT * EMB];
__device__ __nv_bfloat16 g_Vh[(size_t)TOT * EMB],  g_Vl[(size_t)TOT * EMB];
__device__ int g_perm[TOT];
__device__ int g_n1;
__device__ __align__(16) __nv_bfloat16 g_zero16[8];   // zero-initialized

// ---------------------------------------------------------------------------
__device__ __forceinline__ uint32_t pack_bf16(float x, float y) {
    __nv_bfloat162 h = __floats2bfloat162_rn(x, y);
    return *reinterpret_cast<uint32_t*>(&h);
}
__device__ __forceinline__ float bf16_hi_f(float x) {
    return __bfloat162float(__float2bfloat16_rn(x));
}
__device__ __forceinline__ void mma_bf16(float* c, const uint32_t* a, const uint32_t* b) {
    asm volatile(
        "mma.sync.aligned.m16n8k16.row.col.f32.bf16.bf16.f32 "
        "{%0,%1,%2,%3}, {%4,%5,%6,%7}, {%8,%9}, {%0,%1,%2,%3};"
        : "+f"(c[0]), "+f"(c[1]), "+f"(c[2]), "+f"(c[3])
        : "r"(a[0]), "r"(a[1]), "r"(a[2]), "r"(a[3]), "r"(b[0]), "r"(b[1]));
}
__device__ __forceinline__ void ldm_x4(uint32_t* r, uint32_t a) {
    asm volatile("ldmatrix.sync.aligned.m8n8.x4.shared.b16 {%0,%1,%2,%3}, [%4];"
        : "=r"(r[0]), "=r"(r[1]), "=r"(r[2]), "=r"(r[3]) : "r"(a));
}
__device__ __forceinline__ void ldm_x4t(uint32_t* r, uint32_t a) {
    asm volatile("ldmatrix.sync.aligned.m8n8.x4.trans.shared.b16 {%0,%1,%2,%3}, [%4];"
        : "=r"(r[0]), "=r"(r[1]), "=r"(r[2]), "=r"(r[3]) : "r"(a));
}
__device__ __forceinline__ uint32_t smaddr(const void* p) {
    return (uint32_t)__cvta_generic_to_shared(p);
}
#define CPA16(dst, src) \
    asm volatile("cp.async.cg.shared.global [%0], [%1], 16;" :: "r"(dst), "l"(src))
#define CPA_COMMIT() asm volatile("cp.async.commit_group;")
#define CPA_WAIT(n)  asm volatile("cp.async.wait_group %0;" :: "n"(n))

__device__ __forceinline__ void cvt_store4(float4 v, __nv_bfloat16* hi, __nv_bfloat16* lo) {
    float hx = bf16_hi_f(v.x), hy = bf16_hi_f(v.y);
    float hz = bf16_hi_f(v.z), hw = bf16_hi_f(v.w);
    *reinterpret_cast<uint2*>(hi) = make_uint2(pack_bf16(v.x, v.y), pack_bf16(v.z, v.w));
    *reinterpret_cast<uint2*>(lo) = make_uint2(pack_bf16(v.x - hx, v.y - hy),
                                               pack_bf16(v.z - hz, v.w - hw));
}

// ---------------------------------------------------------------------------
// Stable partition of rows by label (lab=1 first). One block, deterministic.
// ---------------------------------------------------------------------------
__global__ __launch_bounds__(512) void partition_kernel(
    const int* __restrict__ labels, int* __restrict__ perm, int* __restrict__ n1out)
{
    __shared__ int s[512];
    __shared__ int tot1;
    int tid = threadIdx.x;
    int base = tid * 32;
    int c = 0;
#pragma unroll
    for (int i = 0; i < 32; i++) c += labels[base + i];
    s[tid] = c;
    __syncthreads();
    for (int off = 1; off < 512; off <<= 1) {
        int v = (tid >= off) ? s[tid - off] : 0;
        __syncthreads();
        if (tid >= off) s[tid] += v;
        __syncthreads();
    }
    int incl = s[tid];
    int excl = incl - c;
    if (tid == 511) { tot1 = incl; *n1out = incl; }
    __syncthreads();
    int p1 = excl;
    int p0 = tot1 + base - excl;
    for (int i = 0; i < 32; i++) {
        int g = base + i;
        if (labels[g]) perm[p1++] = g;
        else           perm[p0++] = g;
    }
}

// ---------------------------------------------------------------------------
// Gather: emits half planes [g,512] and query planes [g,512]
// ---------------------------------------------------------------------------
__global__ __launch_bounds__(128) void gather_kernel(
    const int* __restrict__ item_inputs, const int* __restrict__ skill_inputs,
    const int* __restrict__ item_ids, const int* __restrict__ skill_ids,
    const float* __restrict__ item_emb, const float* __restrict__ skill_emb,
    __nv_bfloat16* __restrict__ Hh, __nv_bfloat16* __restrict__ Hl,
    __nv_bfloat16* __restrict__ QRh, __nv_bfloat16* __restrict__ QRl)
{
    int g = blockIdx.x;
    int t = threadIdx.x;
    size_t hb = (size_t)g * 512, qb = (size_t)g * 512;
    if (t < 64) {
        const float4* ie = reinterpret_cast<const float4*>(item_emb + (size_t)item_inputs[g] * 256);
        cvt_store4(ie[t], Hh + hb + t * 4, Hl + hb + t * 4);
        const float4* qe = reinterpret_cast<const float4*>(item_emb + (size_t)item_ids[g] * 256);
        cvt_store4(qe[t], QRh + qb + t * 4, QRl + qb + t * 4);
    } else {
        int u = t - 64;
        const float4* se = reinterpret_cast<const float4*>(skill_emb + (size_t)skill_inputs[g] * 256);
        cvt_store4(se[u], Hh + hb + 256 + u * 4, Hl + hb + 256 + u * 4);
        const float4* qs = reinterpret_cast<const float4*>(skill_emb + (size_t)skill_ids[g] * 256);
        cvt_store4(qs[u], QRh + qb + 256 + u * 4, QRl + qb + 256 + u * 4);
    }
}

// ---------------------------------------------------------------------------
// Unified weight transpose (+ bf16 hi/lo split), 8 z-slices.
// z=0,1: W_in [1024,512] y-halves. z=2..7: QKV [512,512]. N=512 throughout.
// ---------------------------------------------------------------------------
struct TrAll {
    const float* src[8];
    __nv_bfloat16* dhi[8];
    __nv_bfloat16* dlo[8];
    int K[8];
    int yoff[8];
};
__global__ __launch_bounds__(256) void transpose_all_kernel(TrAll a)
{
    __shared__ float t[32][33];
    int z = blockIdx.z;
    const float* src = a.src[z];
    __nv_bfloat16* dhi = a.dhi[z];
    __nv_bfloat16* dlo = a.dlo[z];
    int K = a.K[z];
    int bx = blockIdx.x * 32;
    int by = (blockIdx.y + a.yoff[z]) * 32;
    int x = threadIdx.x & 31, y0 = threadIdx.x >> 5;
#pragma unroll
    for (int j = 0; j < 32; j += 8)
        t[y0 + j][x] = src[(size_t)(by + y0 + j) * 512 + bx + x];
    __syncthreads();
#pragma unroll
    for (int j = 0; j < 32; j += 8) {
        float v = t[x][y0 + j];
        float h = bf16_hi_f(v);
        size_t idx = (size_t)(bx + y0 + j) * K + by + x;
        dhi[idx] = __float2bfloat16_rn(v);
        dlo[idx] = __float2bfloat16_rn(v - h);
    }
}

// ---------------------------------------------------------------------------
// GEMM shared machinery: 128x128 tile, 8 warps, K-chunk 32, double buffer.
// ---------------------------------------------------------------------------
#define RSTR 40
#define PLANE_B (128 * RSTR * 2)
#define STAGE_B (4 * PLANE_B)
#define GEMM_SMEM (2 * STAGE_B)

__device__ __forceinline__ void gemm_chunk_pipe(
    uint32_t cur, float (&acc)[4][4][4], int wm, int wn,
    int lm, int kq, int nb, int kb2, bool tail_sync)
{
    uint32_t a_u = cur;
    uint32_t b_u = cur + 2 * PLANE_B;

    uint32_t bfh[2][4][2], bfl[2][4][2];
#pragma unroll
    for (int s = 0; s < 2; s++)
#pragma unroll
        for (int jp = 0; jp < 2; jp++) {
            uint32_t off = (uint32_t)((wn + jp * 16 + nb) * RSTR + s * 16 + kb2) * 2;
            uint32_t r[4];
            ldm_x4(r, b_u + off);
            bfh[s][jp * 2][0] = r[0]; bfh[s][jp * 2][1] = r[1];
            bfh[s][jp * 2 + 1][0] = r[2]; bfh[s][jp * 2 + 1][1] = r[3];
            ldm_x4(r, b_u + PLANE_B + off);
            bfl[s][jp * 2][0] = r[0]; bfl[s][jp * 2][1] = r[1];
            bfl[s][jp * 2 + 1][0] = r[2]; bfl[s][jp * 2 + 1][1] = r[3];
        }

    uint32_t ah[2][4], al[2][4];
    {
        uint32_t off0 = (uint32_t)((wm + lm) * RSTR + kq) * 2;
        ldm_x4(ah[0], a_u + off0);
        ldm_x4(al[0], a_u + PLANE_B + off0);
    }
#pragma unroll
    for (int t = 0; t < 8; t++) {
        const int s = t >> 2, i = t & 3;
        const int cb = t & 1;
        if (t < 7) {
            const int tn = t + 1, sn = tn >> 2, in = tn & 3;
            uint32_t offn = (uint32_t)((wm + in * 16 + lm) * RSTR + sn * 16 + kq) * 2;
            ldm_x4(ah[cb ^ 1], a_u + offn);
            ldm_x4(al[cb ^ 1], a_u + PLANE_B + offn);
        } else if (tail_sync) {
            CPA_WAIT(0);
            __syncthreads();
        }
#pragma unroll
        for (int j = 0; j < 4; j++) mma_bf16(acc[i][j], ah[cb], bfh[s][j]);
#pragma unroll
        for (int j = 0; j < 4; j++) mma_bf16(acc[i][j], al[cb], bfh[s][j]);
#pragma unroll
        for (int j = 0; j < 4; j++) mma_bf16(acc[i][j], ah[cb], bfl[s][j]);
    }
}

// ---------------------------------------------------------------------------
// Phase-1 fused launch: z=0 MLP (partitioned rows, K=512/pass, weight-half
// select), z=1 Q1 proj, z=2 Q2 proj. All depend only on gather+transpose.
// ---------------------------------------------------------------------------
struct P1Args {
    // MLP
    const __nv_bfloat16 *Hh, *Hl, *Wh, *Wl;
    const float* mbias;
    __nv_bfloat16 *Xh, *Xl;
    const int *perm, *n1p;
    // Q projections (z-1 in {0,1})
    const __nv_bfloat16 *Ah[2], *Al[2], *Bh[2], *Bl[2];
    const float* bias[2];
    __nv_bfloat16 *Ch[2], *Cl[2];
};
__global__ __launch_bounds__(256, 2)
void gemm_phase1_kernel(P1Args a)
{
    extern __shared__ __align__(16) char dsm[];
    int tid = threadIdx.x;
    int wid = tid >> 5, lane = tid & 31;
    int g = lane >> 2, t = lane & 3;
    int bm = blockIdx.y * 128, bn = blockIdx.x * 128;
    int wm = (wid & 1) * 64, wn = (wid >> 1) * 32;
    int lm = lane & 15, kq = (lane >> 4) << 3;
    int nb = (lane & 7) + ((lane >> 4) << 3);
    int kb2 = ((lane >> 3) & 1) * 8;

    int fr[2], fc[2];
#pragma unroll
    for (int i = 0; i < 2; i++) { int f = tid + i * 256; fr[i] = f >> 2; fc[i] = (f & 3) * 8; }

    float acc[4][4][4];
#pragma unroll
    for (int i = 0; i < 4; i++)
#pragma unroll
        for (int j = 0; j < 4; j++)
#pragma unroll
            for (int r = 0; r < 4; r++) acc[i][j][r] = 0.f;

    if (blockIdx.z == 0) {
        // ------------------------- MLP mode -------------------------
        int n1 = *a.n1p;
        int mode = (bm + 128 <= n1) ? 0 : ((bm >= n1) ? 1 : 2);
        int NC = (mode == 2) ? 32 : 16;

        const __nv_bfloat16* rAh[2];
        const __nv_bfloat16* rAl[2];
        bool is1[2];
#pragma unroll
        for (int i = 0; i < 2; i++) {
            int pos = bm + fr[i];
            int pr = a.perm[pos];
            rAh[i] = a.Hh + (size_t)pr * 512;
            rAl[i] = a.Hl + (size_t)pr * 512;
            is1[i] = pos < n1;
        }

        auto load_stage = [&](uint32_t st, int ci) {
            int pass = (mode == 2) ? (ci >> 4) : mode;
            int k0 = (ci & 15) << 5;
            const __nv_bfloat16* Bh = a.Wh + (pass ? 512 : 0);
            const __nv_bfloat16* Bl = a.Wl + (pass ? 512 : 0);
#pragma unroll
            for (int i = 0; i < 2; i++) {
                uint32_t doff = (uint32_t)(fr[i] * RSTR + fc[i]) * 2;
                bool on = (mode != 2) || ((pass == 0) ? is1[i] : !is1[i]);
                const __nv_bfloat16* sah = on ? (rAh[i] + k0 + fc[i]) : g_zero16;
                const __nv_bfloat16* sal = on ? (rAl[i] + k0 + fc[i]) : g_zero16;
                CPA16(st + doff, sah);
                CPA16(st + PLANE_B + doff, sal);
                size_t gb = (size_t)(bn + fr[i]) * 1024 + k0 + fc[i];
                CPA16(st + 2 * PLANE_B + doff, Bh + gb);
                CPA16(st + 3 * PLANE_B + doff, Bl + gb);
            }
            CPA_COMMIT();
        };

        load_stage(smaddr(dsm), 0);
        CPA_WAIT(0);
        __syncthreads();
        for (int chunk = 0; chunk < NC; chunk++) {
            uint32_t cur = smaddr(dsm) + (chunk & 1) * STAGE_B;
            bool more = (chunk + 1 < NC);
            if (more)
                load_stage(smaddr(dsm) + ((chunk + 1) & 1) * STAGE_B, chunk + 1);
            gemm_chunk_pipe(cur, acc, wm, wn, lm, kq, nb, kb2, more);
        }

#pragma unroll
        for (int i = 0; i < 4; i++) {
            int pos0 = bm + wm + i * 16 + g;
            int orow0 = a.perm[pos0];
            int orow1 = a.perm[pos0 + 8];
#pragma unroll
            for (int j = 0; j < 4; j++) {
                int col = bn + wn + j * 8 + t * 2;
                float2 bv = *reinterpret_cast<const float2*>(a.mbias + col);
                float v0 = fmaxf(acc[i][j][0] + bv.x, 0.f);
                float v1 = fmaxf(acc[i][j][1] + bv.y, 0.f);
                float v2 = fmaxf(acc[i][j][2] + bv.x, 0.f);
                float v3 = fmaxf(acc[i][j][3] + bv.y, 0.f);
                size_t i0 = (size_t)orow0 * 512 + col;
                size_t i1 = (size_t)orow1 * 512 + col;
                *reinterpret_cast<uint32_t*>(a.Xh + i0) = pack_bf16(v0, v1);
                *reinterpret_cast<uint32_t*>(a.Xl + i0) =
                    pack_bf16(v0 - bf16_hi_f(v0), v1 - bf16_hi_f(v1));
                *reinterpret_cast<uint32_t*>(a.Xh + i1) = pack_bf16(v2, v3);
                *reinterpret_cast<uint32_t*>(a.Xl + i1) =
                    pack_bf16(v2 - bf16_hi_f(v2), v3 - bf16_hi_f(v3));
            }
        }
    } else {
        // ------------------------- proj mode -------------------------
        int z = blockIdx.z - 1;
        const __nv_bfloat16* Ah = a.Ah[z];
        const __nv_bfloat16* Al = a.Al[z];
        const __nv_bfloat16* Bthi = a.Bh[z];
        const __nv_bfloat16* Btlo = a.Bl[z];
        const float* bias = a.bias[z];
        __nv_bfloat16* Chi = a.Ch[z];
        __nv_bfloat16* Clo = a.Cl[z];
        const int K = 512, NC = 16;

        auto load_stage = [&](uint32_t st, int k0) {
#pragma unroll
            for (int i = 0; i < 2; i++) {
                uint32_t doff = (uint32_t)(fr[i] * RSTR + fc[i]) * 2;
                size_t ga = (size_t)(bm + fr[i]) * K + k0 + fc[i];
                size_t gb = (size_t)(bn + fr[i]) * K + k0 + fc[i];
                CPA16(st + doff, Ah + ga);
                CPA16(st + PLANE_B + doff, Al + ga);
                CPA16(st + 2 * PLANE_B + doff, Bthi + gb);
                CPA16(st + 3 * PLANE_B + doff, Btlo + gb);
            }
            CPA_COMMIT();
        };

        load_stage(smaddr(dsm), 0);
        CPA_WAIT(0);
        __syncthreads();
        for (int chunk = 0; chunk < NC; chunk++) {
            uint32_t cur = smaddr(dsm) + (chunk & 1) * STAGE_B;
            bool more = (chunk + 1 < NC);
            if (more)
                load_stage(smaddr(dsm) + ((chunk + 1) & 1) * STAGE_B, (chunk + 1) << 5);
            gemm_chunk_pipe(cur, acc, wm, wn, lm, kq, nb, kb2, more);
        }

#pragma unroll
        for (int i = 0; i < 4; i++) {
            int row0 = bm + wm + i * 16 + g;
#pragma unroll
            for (int j = 0; j < 4; j++) {
                int col = bn + wn + j * 8 + t * 2;
                float2 bv = *reinterpret_cast<const float2*>(bias + col);
                float v0 = acc[i][j][0] + bv.x, v1 = acc[i][j][1] + bv.y;
                float v2 = acc[i][j][2] + bv.x, v3 = acc[i][j][3] + bv.y;
                size_t i0 = (size_t)row0 * 512 + col;
                size_t i1 = (size_t)(row0 + 8) * 512 + col;
                *reinterpret_cast<uint32_t*>(Chi + i0) = pack_bf16(v0, v1);
                *reinterpret_cast<uint32_t*>(Clo + i0) =
                    pack_bf16(v0 - bf16_hi_f(v0), v1 - bf16_hi_f(v1));
                *reinterpret_cast<uint32_t*>(Chi + i1) = pack_bf16(v2, v3);
                *reinterpret_cast<uint32_t*>(Clo + i1) =
                    pack_bf16(v2 - bf16_hi_f(v2), v3 - bf16_hi_f(v3));
            }
        }
    }
}

// ---------------------------------------------------------------------------
// Fused projections (K/V): z selects problem (K=512), plane output.
// ---------------------------------------------------------------------------
struct QKVArgs {
    const __nv_bfloat16* Ah[2];
    const __nv_bfloat16* Al[2];
    const __nv_bfloat16* Bh[2];
    const __nv_bfloat16* Bl[2];
    const float* bias[2];
    __nv_bfloat16* Ch[2];
    __nv_bfloat16* Cl[2];
};
__global__ __launch_bounds__(256, 2)
void gemm_qkv_kernel(QKVArgs args)
{
    extern __shared__ __align__(16) char dsm[];
    const int K = 512;
    int z = blockIdx.z;
    const __nv_bfloat16* Ah = args.Ah[z];
    const __nv_bfloat16* Al = args.Al[z];
    const __nv_bfloat16* Bthi = args.Bh[z];
    const __nv_bfloat16* Btlo = args.Bl[z];
    const float* bias = args.bias[z];
    __nv_bfloat16* Chi = args.Ch[z];
    __nv_bfloat16* Clo = args.Cl[z];

    int tid = threadIdx.x;
    int wid = tid >> 5, lane = tid & 31;
    int g = lane >> 2, t = lane & 3;
    int bm = blockIdx.y * 128, bn = blockIdx.x * 128;
    int wm = (wid & 1) * 64, wn = (wid >> 1) * 32;
    const int NC = 16;
    int lm = lane & 15, kq = (lane >> 4) << 3;
    int nb = (lane & 7) + ((lane >> 4) << 3);
    int kb2 = ((lane >> 3) & 1) * 8;

    int fr[2], fc[2];
#pragma unroll
    for (int i = 0; i < 2; i++) { int f = tid + i * 256; fr[i] = f >> 2; fc[i] = (f & 3) * 8; }

    float acc[4][4][4];
#pragma unroll
    for (int i = 0; i < 4; i++)
#pragma unroll
        for (int j = 0; j < 4; j++)
#pragma unroll
            for (int r = 0; r < 4; r++) acc[i][j][r] = 0.f;

    auto load_stage = [&](uint32_t st, int k0) {
#pragma unroll
        for (int i = 0; i < 2; i++) {
            uint32_t doff = (uint32_t)(fr[i] * RSTR + fc[i]) * 2;
            size_t ga = (size_t)(bm + fr[i]) * K + k0 + fc[i];
            size_t gb = (size_t)(bn + fr[i]) * K + k0 + fc[i];
            CPA16(st + doff, Ah + ga);
            CPA16(st + PLANE_B + doff, Al + ga);
            CPA16(st + 2 * PLANE_B + doff, Bthi + gb);
            CPA16(st + 3 * PLANE_B + doff, Btlo + gb);
        }
        CPA_COMMIT();
    };

    load_stage(smaddr(dsm), 0);
    CPA_WAIT(0);
    __syncthreads();

    for (int chunk = 0; chunk < NC; chunk++) {
        uint32_t cur = smaddr(dsm) + (chunk & 1) * STAGE_B;
        bool more = (chunk + 1 < NC);
        if (more)
            load_stage(smaddr(dsm) + ((chunk + 1) & 1) * STAGE_B, (chunk + 1) << 5);
        gemm_chunk_pipe(cur, acc, wm, wn, lm, kq, nb, kb2, more);
    }

#pragma unroll
    for (int i = 0; i < 4; i++) {
        int row0 = bm + wm + i * 16 + g;
#pragma unroll
        for (int j = 0; j < 4; j++) {
            int col = bn + wn + j * 8 + t * 2;
            float2 bv = *reinterpret_cast<const float2*>(bias + col);
            float v0 = acc[i][j][0] + bv.x, v1 = acc[i][j][1] + bv.y;
            float v2 = acc[i][j][2] + bv.x, v3 = acc[i][j][3] + bv.y;
            size_t i0 = (size_t)row0 * 512 + col;
            size_t i1 = (size_t)(row0 + 8) * 512 + col;
            *reinterpret_cast<uint32_t*>(Chi + i0) = pack_bf16(v0, v1);
            *reinterpret_cast<uint32_t*>(Clo + i0) =
                pack_bf16(v0 - bf16_hi_f(v0), v1 - bf16_hi_f(v1));
            *reinterpret_cast<uint32_t*>(Chi + i1) = pack_bf16(v2, v3);
            *reinterpret_cast<uint32_t*>(Clo + i1) =
                pack_bf16(v2 - bf16_hi_f(v2), v3 - bf16_hi_f(v3));
        }
    }
}

// ---------------------------------------------------------------------------
// Flash attention: cp.async double-buffered K/V, Q frags in registers.
// CTA = balanced pair of q-tiles (3,0)/(2,1) -> 10 KV tiles each.
// OUT=0: write f32 Op + planes. OUT=1: Op += relu(result).
// ---------------------------------------------------------------------------
#define QS 72
#define FPL (64 * QS)
#define FSTG_B (4 * FPL * 2)
#define FL_SMEM (2 * FSTG_B)

template<int OUT>
__global__ __launch_bounds__(256, 2) void flash_bf16_kernel(
    const __nv_bfloat16* __restrict__ Qh, const __nv_bfloat16* __restrict__ Ql,
    const __nv_bfloat16* __restrict__ Kh, const __nv_bfloat16* __restrict__ Kl,
    const __nv_bfloat16* __restrict__ Vh, const __nv_bfloat16* __restrict__ Vl,
    float* __restrict__ Op,
    __nv_bfloat16* __restrict__ Ohp, __nv_bfloat16* __restrict__ Olp)
{
    extern __shared__ __align__(16) char fsm[];

    int tid = threadIdx.x;
    int wid = tid >> 5, lane = tid & 31;
    int g = lane >> 2, t = lane & 3;
    int qtx = blockIdx.x;
    int h = blockIdx.y, b = blockIdx.z;
    size_t kvoff = ((size_t)b * SEQ) * EMB + h * DHD;

    int rb = wid * 16;
    int lm = lane & 15, kq = (lane >> 4) << 3;
    int nbk = (lane & 7) + ((lane >> 4) << 3);
    int kb2 = ((lane >> 3) & 1) * 8;
    int kv = (lane & 7) + ((lane >> 3) & 1) * 8;
    int nv = (lane >> 4) << 3;

    int fr[2], fc[2];
#pragma unroll
    for (int i = 0; i < 2; i++) {
        int f = tid + i * 256;
        fr[i] = f >> 3; fc[i] = (f & 7) * 8;
    }

    for (int pass = 0; pass < 2; pass++) {
        int qt = (pass == 0) ? (3 - qtx) : qtx;
        size_t qoff = ((size_t)(b * SEQ + qt * 128)) * EMB + h * DHD;

        uint32_t qah[4][4], qal[4][4];
        {
            __nv_bfloat16* sQh = reinterpret_cast<__nv_bfloat16*>(fsm);
            __nv_bfloat16* sQl = sQh + 128 * QS;
#pragma unroll
            for (int i = 0; i < 4; i++) {
                int f = tid + i * 256;
                int r = f >> 3, c = (f & 7) * 8;
                *reinterpret_cast<uint4*>(sQh + r * QS + c) =
                    *reinterpret_cast<const uint4*>(Qh + qoff + (size_t)r * EMB + c);
                *reinterpret_cast<uint4*>(sQl + r * QS + c) =
                    *reinterpret_cast<const uint4*>(Ql + qoff + (size_t)r * EMB + c);
            }
            __syncthreads();
            uint32_t uQh = smaddr(sQh), uQl = smaddr(sQl);
#pragma unroll
            for (int kk = 0; kk < 4; kk++) {
                uint32_t qo = (uint32_t)((rb + lm) * QS + kk * 16 + kq) * 2;
                ldm_x4(qah[kk], uQh + qo);
                ldm_x4(qal[kk], uQl + qo);
            }
            __syncthreads();
        }

        int ktmax = qt * 2 + 1;
        int wmaxrow = qt * 128 + rb + 15;
        int row0g = qt * 128 + rb + g, row1g = row0g + 8;

        {
            uint32_t st = smaddr(fsm);
#pragma unroll
            for (int i = 0; i < 2; i++) {
                uint32_t doff = (uint32_t)(fr[i] * QS + fc[i]) * 2;
                size_t go = kvoff + (size_t)fr[i] * EMB + fc[i];
                CPA16(st + doff, Kh + go);
                CPA16(st + FPL * 2 + doff, Kl + go);
                CPA16(st + 2 * FPL * 2 + doff, Vh + go);
                CPA16(st + 3 * FPL * 2 + doff, Vl + go);
            }
            CPA_COMMIT();
        }

        float m0 = -INFINITY, m1 = -INFINITY, l0 = 0.f, l1 = 0.f;
        float acc[8][4];
#pragma unroll
        for (int j = 0; j < 8; j++)
#pragma unroll
            for (int r = 0; r < 4; r++) acc[j][r] = 0.f;

        for (int kt = 0; kt <= ktmax; kt++) {
            uint32_t cur = smaddr(fsm) + (kt & 1) * FSTG_B;
            bool more = (kt < ktmax);
            if (more) {
                uint32_t nxt = smaddr(fsm) + ((kt + 1) & 1) * FSTG_B;
                size_t ko = kvoff + (size_t)(kt + 1) * 64 * EMB;
#pragma unroll
                for (int i = 0; i < 2; i++) {
                    uint32_t doff = (uint32_t)(fr[i] * QS + fc[i]) * 2;
                    size_t go = ko + (size_t)fr[i] * EMB + fc[i];
                    CPA16(nxt + doff, Kh + go);
                    CPA16(nxt + FPL * 2 + doff, Kl + go);
                    CPA16(nxt + 2 * FPL * 2 + doff, Vh + go);
                    CPA16(nxt + 3 * FPL * 2 + doff, Vl + go);
                }
                CPA_COMMIT();
                CPA_WAIT(1);
            } else {
                CPA_WAIT(0);
            }
            __syncthreads();

            if (kt * 64 <= wmaxrow) {
                uint32_t uKh = cur, uKl = cur + FPL * 2;
                uint32_t uVh = cur + 2 * FPL * 2, uVl = cur + 3 * FPL * 2;

                float s[8][4];
#pragma unroll
                for (int j = 0; j < 8; j++)
#pragma unroll
                    for (int r = 0; r < 4; r++) s[j][r] = 0.f;
#pragma unroll
                for (int kk = 0; kk < 4; kk++) {
#pragma unroll
                    for (int jp = 0; jp < 4; jp++) {
                        uint32_t koff = (uint32_t)((jp * 16 + nbk) * QS + kk * 16 + kb2) * 2;
                        uint32_t rh[4], rl[4];
                        ldm_x4(rh, uKh + koff);
                        ldm_x4(rl, uKl + koff);
                        uint32_t b0[2] = { rh[0], rh[1] }, b1[2] = { rh[2], rh[3] };
                        uint32_t c0[2] = { rl[0], rl[1] }, c1[2] = { rl[2], rl[3] };
                        mma_bf16(s[2 * jp],     qah[kk], b0);
                        mma_bf16(s[2 * jp + 1], qah[kk], b1);
                        mma_bf16(s[2 * jp],     qal[kk], b0);
                        mma_bf16(s[2 * jp + 1], qal[kk], b1);
                        mma_bf16(s[2 * jp],     qah[kk], c0);
                        mma_bf16(s[2 * jp + 1], qah[kk], c1);
                    }
                }

                int colb = kt * 64 + t * 2;
#pragma unroll
                for (int j = 0; j < 8; j++) {
                    int c0 = colb + j * 8, c1 = c0 + 1;
                    s[j][0] = (c0 > row0g) ? -INFINITY : s[j][0] * ATTN_SCALE;
                    s[j][1] = (c1 > row0g) ? -INFINITY : s[j][1] * ATTN_SCALE;
                    s[j][2] = (c0 > row1g) ? -INFINITY : s[j][2] * ATTN_SCALE;
                    s[j][3] = (c1 > row1g) ? -INFINITY : s[j][3] * ATTN_SCALE;
                }

                float tm0 = -INFINITY, tm1 = -INFINITY;
#pragma unroll
                for (int j = 0; j < 8; j++) {
                    tm0 = fmaxf(tm0, fmaxf(s[j][0], s[j][1]));
                    tm1 = fmaxf(tm1, fmaxf(s[j][2], s[j][3]));
                }
                tm0 = fmaxf(tm0, __shfl_xor_sync(0xFFFFFFFFu, tm0, 1));
                tm0 = fmaxf(tm0, __shfl_xor_sync(0xFFFFFFFFu, tm0, 2));
                tm1 = fmaxf(tm1, __shfl_xor_sync(0xFFFFFFFFu, tm1, 1));
                tm1 = fmaxf(tm1, __shfl_xor_sync(0xFFFFFFFFu, tm1, 2));
                float m0n = fmaxf(m0, tm0), m1n = fmaxf(m1, tm1);
                float ms0 = fmaxf(m0n, -1e30f), ms1 = fmaxf(m1n, -1e30f);
                float alpha0 = __expf(m0 - ms0), alpha1 = __expf(m1 - ms1);
                m0 = m0n; m1 = m1n;
#pragma unroll
                for (int j = 0; j < 8; j++) {
                    acc[j][0] *= alpha0; acc[j][1] *= alpha0;
                    acc[j][2] *= alpha1; acc[j][3] *= alpha1;
                }

                float ps0 = 0.f, ps1 = 0.f;
#pragma unroll
                for (int kk = 0; kk < 4; kk++) {
                    int j0 = 2 * kk, j1 = 2 * kk + 1;
                    float p00 = __expf(s[j0][0] - ms0), p01 = __expf(s[j0][1] - ms0);
                    float p02 = __expf(s[j0][2] - ms1), p03 = __expf(s[j0][3] - ms1);
                    float p10 = __expf(s[j1][0] - ms0), p11 = __expf(s[j1][1] - ms0);
                    float p12 = __expf(s[j1][2] - ms1), p13 = __expf(s[j1][3] - ms1);
                    ps0 += p00 + p01 + p10 + p11;
                    ps1 += p02 + p03 + p12 + p13;
                    uint32_t pah[4], pal[4];
                    pah[0] = pack_bf16(p00, p01);
                    pah[1] = pack_bf16(p02, p03);
                    pah[2] = pack_bf16(p10, p11);
                    pah[3] = pack_bf16(p12, p13);
                    pal[0] = pack_bf16(p00 - bf16_hi_f(p00), p01 - bf16_hi_f(p01));
                    pal[1] = pack_bf16(p02 - bf16_hi_f(p02), p03 - bf16_hi_f(p03));
                    pal[2] = pack_bf16(p10 - bf16_hi_f(p10), p11 - bf16_hi_f(p11));
                    pal[3] = pack_bf16(p12 - bf16_hi_f(p12), p13 - bf16_hi_f(p13));
#pragma unroll
                    for (int jdp = 0; jdp < 4; jdp++) {
                        uint32_t voff = (uint32_t)((kk * 16 + kv) * QS + jdp * 16 + nv) * 2;
                        uint32_t rh[4], rl[4];
                        ldm_x4t(rh, uVh + voff);
                        ldm_x4t(rl, uVl + voff);
                        uint32_t b0[2] = { rh[0], rh[1] }, b1[2] = { rh[2], rh[3] };
                        uint32_t c0[2] = { rl[0], rl[1] }, c1[2] = { rl[2], rl[3] };
                        mma_bf16(acc[2 * jdp],     pah, b0);
                        mma_bf16(acc[2 * jdp + 1], pah, b1);
                        mma_bf16(acc[2 * jdp],     pal, b0);
                        mma_bf16(acc[2 * jdp + 1], pal, b1);
                        mma_bf16(acc[2 * jdp],     pah, c0);
                        mma_bf16(acc[2 * jdp + 1], pah, c1);
                    }
                }
                ps0 += __shfl_xor_sync(0xFFFFFFFFu, ps0, 1);
                ps0 += __shfl_xor_sync(0xFFFFFFFFu, ps0, 2);
                ps1 += __shfl_xor_sync(0xFFFFFFFFu, ps1, 1);
                ps1 += __shfl_xor_sync(0xFFFFFFFFu, ps1, 2);
                l0 = l0 * alpha0 + ps0;
                l1 = l1 * alpha1 + ps1;
            }
            __syncthreads();
        }

        float inv0 = 1.f / l0, inv1 = 1.f / l1;
#pragma unroll
        for (int jd = 0; jd < 8; jd++) {
            int c = jd * 8 + t * 2;
            size_t i0 = qoff + (size_t)(rb + g) * EMB + c;
            size_t i1 = qoff + (size_t)(rb + g + 8) * EMB + c;
            float o00 = acc[jd][0] * inv0, o01 = acc[jd][1] * inv0;
            float o10 = acc[jd][2] * inv1, o11 = acc[jd][3] * inv1;
            if (OUT == 0) {
                *reinterpret_cast<float2*>(Op + i0) = make_float2(o00, o01);
                *reinterpret_cast<float2*>(Op + i1) = make_float2(o10, o11);
                *reinterpret_cast<uint32_t*>(Ohp + i0) = pack_bf16(o00, o01);
                *reinterpret_cast<uint32_t*>(Olp + i0) =
                    pack_bf16(o00 - bf16_hi_f(o00), o01 - bf16_hi_f(o01));
                *reinterpret_cast<uint32_t*>(Ohp + i1) = pack_bf16(o10, o11);
                *reinterpret_cast<uint32_t*>(Olp + i1) =
                    pack_bf16(o10 - bf16_hi_f(o10), o11 - bf16_hi_f(o11));
            } else {
                float2 e0 = *reinterpret_cast<float2*>(Op + i0);
                float2 e1 = *reinterpret_cast<float2*>(Op + i1);
                *reinterpret_cast<float2*>(Op + i0) =
                    make_float2(e0.x + fmaxf(o00, 0.f), e0.y + fmaxf(o01, 0.f));
                *reinterpret_cast<float2*>(Op + i1) =
                    make_float2(e1.x + fmaxf(o10, 0.f), e1.y + fmaxf(o11, 0.f));
            }
        }
    }
}

// ---------------------------------------------------------------------------
__global__ __launch_bounds__(256) void out_proj_kernel(
    const float* __restrict__ out, const float* __restrict__ Wout,
    const float* __restrict__ bout, float* __restrict__ y)
{
    int g = blockIdx.x * 8 + (threadIdx.x >> 5);
    int lane = threadIdx.x & 31;
    const float4* o4 = reinterpret_cast<const float4*>(out + (size_t)g * EMB);
    const float4* w4 = reinterpret_cast<const float4*>(Wout);
    float s = 0.f;
#pragma unroll
    for (int i = 0; i < 4; i++) {
        float4 a = o4[lane + 32 * i];
        float4 b = w4[lane + 32 * i];
        s += a.x * b.x + a.y * b.y + a.z * b.z + a.w * b.w;
    }
#pragma unroll
    for (int off = 16; off > 0; off >>= 1)
        s += __shfl_xor_sync(0xFFFFFFFFu, s, off);
    if (lane == 0) y[g] = s + bout[0];
}

// ---------------------------------------------------------------------------
extern "C" void kernel_launch(void* const* d_in, const int* in_sizes, int n_in,
                              void* d_out, int out_size)
{
    const int*   item_inputs  = (const int*)d_in[0];
    const int*   skill_inputs = (const int*)d_in[1];
    const int*   label_inputs = (const int*)d_in[2];
    const int*   item_ids     = (const int*)d_in[3];
    const int*   skill_ids    = (const int*)d_in[4];
    const float* item_emb     = (const float*)d_in[5];
    const float* skill_emb    = (const float*)d_in[6];
    const float* W_in         = (const float*)d_in[7];
    const float* b_in         = (const float*)d_in[8];
    const float* Wq           = (const float*)d_in[9];
    const float* bq           = (const float*)d_in[10];
    const float* Wk           = (const float*)d_in[11];
    const float* bk           = (const float*)d_in[12];
    const float* Wv           = (const float*)d_in[13];
    const float* bv           = (const float*)d_in[14];
    const float* W_out        = (const float*)d_in[22];
    const float* b_out        = (const float*)d_in[23];
    float* y = (float*)d_out;

    float* outb;
    __nv_bfloat16 *w, *hh, *hl, *qrh, *qrl, *xh, *xl, *oh, *ol;
    __nv_bfloat16 *q1h, *q1l, *q2h, *q2l, *kh, *kl, *vh, *vl;
    int *perm, *n1;
    cudaGetSymbolAddress((void**)&outb, g_outb);
    cudaGetSymbolAddress((void**)&w,    g_W);
    cudaGetSymbolAddress((void**)&hh,   g_Hh);
    cudaGetSymbolAddress((void**)&hl,   g_Hl);
    cudaGetSymbolAddress((void**)&qrh,  g_QRh);
    cudaGetSymbolAddress((void**)&qrl,  g_QRl);
    cudaGetSymbolAddress((void**)&xh,   g_Xh);
    cudaGetSymbolAddress((void**)&xl,   g_Xl);
    cudaGetSymbolAddress((void**)&oh,   g_Oh);
    cudaGetSymbolAddress((void**)&ol,   g_Ol);
    cudaGetSymbolAddress((void**)&q1h,  g_Q1h);
    cudaGetSymbolAddress((void**)&q1l,  g_Q1l);
    cudaGetSymbolAddress((void**)&q2h,  g_Q2h);
    cudaGetSymbolAddress((void**)&q2l,  g_Q2l);
    cudaGetSymbolAddress((void**)&kh,   g_Kh);
    cudaGetSymbolAddress((void**)&kl,   g_Kl);
    cudaGetSymbolAddress((void**)&vh,   g_Vh);
    cudaGetSymbolAddress((void**)&vl,   g_Vl);
    cudaGetSymbolAddress((void**)&perm, g_perm);
    cudaGetSymbolAddress((void**)&n1,   g_n1);

    cudaFuncSetAttribute(flash_bf16_kernel<0>,
                         cudaFuncAttributeMaxDynamicSharedMemorySize, FL_SMEM);
    cudaFuncSetAttribute(flash_bf16_kernel<1>,
                         cudaFuncAttributeMaxDynamicSharedMemorySize, FL_SMEM);
    cudaFuncSetAttribute(gemm_phase1_kernel,
                         cudaFuncAttributeMaxDynamicSharedMemorySize, GEMM_SMEM);
    cudaFuncSetAttribute(gemm_qkv_kernel,
                         cudaFuncAttributeMaxDynamicSharedMemorySize, GEMM_SMEM);

    __nv_bfloat16* win_hi = w;
    __nv_bfloat16* win_lo = w + 512 * 1024;
    __nv_bfloat16* qkv_hi[2][3];
    __nv_bfloat16* qkv_lo[2][3];
    {
        __nv_bfloat16* p = w + 2 * 512 * 1024;
        for (int l = 0; l < 2; l++)
            for (int m = 0; m < 3; m++) {
                qkv_hi[l][m] = p; p += 512 * 512;
                qkv_lo[l][m] = p; p += 512 * 512;
            }
    }

    // 0: partition
    partition_kernel<<<1, 512>>>(label_inputs, perm, n1);
    // 1: gather
    gather_kernel<<<TOT, 128>>>(item_inputs, skill_inputs,
                                item_ids, skill_ids, item_emb, skill_emb,
                                hh, hl, qrh, qrl);
    // 2: all transposes in one launch (8 z-slices)
    {
        TrAll ta;
        ta.src[0] = W_in; ta.dhi[0] = win_hi; ta.dlo[0] = win_lo; ta.K[0] = 1024; ta.yoff[0] = 0;
        ta.src[1] = W_in; ta.dhi[1] = win_hi; ta.dlo[1] = win_lo; ta.K[1] = 1024; ta.yoff[1] = 16;
        const float* srcs[3] = { Wq, Wk, Wv };
        for (int l = 0; l < 2; l++)
            for (int m = 0; m < 3; m++) {
                int zi = 2 + l * 3 + m;
                ta.src[zi] = srcs[m] + (size_t)l * 512 * 512;
                ta.dhi[zi] = qkv_hi[l][m];
                ta.dlo[zi] = qkv_lo[l][m];
                ta.K[zi] = 512;
                ta.yoff[zi] = 0;
            }
        transpose_all_kernel<<<dim3(16, 16, 8), 256>>>(ta);
    }
    // 3: phase-1 fused GEMMs (MLP + Q1 + Q2)
    {
        P1Args pa;
        pa.Hh = hh; pa.Hl = hl; pa.Wh = win_hi; pa.Wl = win_lo;
        pa.mbias = b_in; pa.Xh = xh; pa.Xl = xl; pa.perm = perm; pa.n1p = n1;
        pa.Ah[0] = qrh; pa.Al[0] = qrl;
        pa.Bh[0] = qkv_hi[0][0]; pa.Bl[0] = qkv_lo[0][0];
        pa.bias[0] = bq; pa.Ch[0] = q1h; pa.Cl[0] = q1l;
        pa.Ah[1] = qrh; pa.Al[1] = qrl;
        pa.Bh[1] = qkv_hi[1][0]; pa.Bl[1] = qkv_lo[1][0];
        pa.bias[1] = bq + EMB; pa.Ch[1] = q2h; pa.Cl[1] = q2l;
        gemm_phase1_kernel<<<dim3(4, 128, 3), 256, GEMM_SMEM>>>(pa);
    }
    // 4: K1,V1
    {
        QKVArgs qa;
        qa.Ah[0] = xh; qa.Al[0] = xl;
        qa.Ah[1] = xh; qa.Al[1] = xl;
        qa.Bh[0] = qkv_hi[0][1]; qa.Bl[0] = qkv_lo[0][1];
        qa.Bh[1] = qkv_hi[0][2]; qa.Bl[1] = qkv_lo[0][2];
        qa.bias[0] = bk; qa.bias[1] = bv;
        qa.Ch[0] = kh; qa.Cl[0] = kl;
        qa.Ch[1] = vh; qa.Cl[1] = vl;
        gemm_qkv_kernel<<<dim3(4, 128, 2), 256, GEMM_SMEM>>>(qa);
    }
    // 5: flash layer 1
    flash_bf16_kernel<0><<<dim3(2, NH, Bsz), 256, FL_SMEM>>>(
        q1h, q1l, kh, kl, vh, vl, outb, oh, ol);
    // 6: K2,V2
    {
        QKVArgs qa;
        qa.Ah[0] = oh; qa.Al[0] = ol;
        qa.Ah[1] = oh; qa.Al[1] = ol;
        qa.Bh[0] = qkv_hi[1][1]; qa.Bl[0] = qkv_lo[1][1];
        qa.Bh[1] = qkv_hi[1][2]; qa.Bl[1] = qkv_lo[1][2];
        qa.bias[0] = bk + EMB; qa.bias[1] = bv + EMB;
        qa.Ch[0] = kh; qa.Cl[0] = kl;
        qa.Ch[1] = vh; qa.Cl[1] = vl;
        gemm_qkv_kernel<<<dim3(4, 128, 2), 256, GEMM_SMEM>>>(qa);
    }
    // 7: flash layer 2 (residual add)
    flash_bf16_kernel<1><<<dim3(2, NH, Bsz), 256, FL_SMEM>>>(
        q2h, q2l, kh, kl, vh, vl, outb, nullptr, nullptr);
    // 8: output projection
    out_proj_kernel<<<TOT / 8, 256>>>(outb, W_out, b_out, y);
}

// round 13
// speedup vs baseline: 1.0222x; 1.0222x over previous
#include <cuda_runtime.h>
#include <cuda_bf16.h>
#include <cstdint>

// ---------------------------------------------------------------------------
// TSAKT: gather -> ReLU MLP -> 2x causal MHA -> output proj.
// glo/ts biases are key-constant pre-mask => softmax-shift-invariant => dropped.
// R13 = R11 (751.5us baseline) + single 8-slice transpose launch only.
// (R12's heterogeneous MLP+Q merge regressed and is reverted.)
// ---------------------------------------------------------------------------

#define Bsz 32
#define SEQ 512
#define EMB 512
#define NH  8
#define DHD 64
#define TOT (Bsz * SEQ)
#define ATTN_SCALE 0.125f

// ---- device scratch ---------------------------------------------------------
__device__ float g_outb [(size_t)TOT * EMB];
__device__ __nv_bfloat16 g_W[2 * 512 * 1024 + 12 * 512 * 512];
__device__ __nv_bfloat16 g_Hh[(size_t)TOT * 512],  g_Hl[(size_t)TOT * 512];
__device__ __nv_bfloat16 g_QRh[(size_t)TOT * EMB], g_QRl[(size_t)TOT * EMB];
__device__ __nv_bfloat16 g_Xh[(size_t)TOT * EMB],  g_Xl[(size_t)TOT * EMB];
__device__ __nv_bfloat16 g_Oh[(size_t)TOT * EMB],  g_Ol[(size_t)TOT * EMB];
__device__ __nv_bfloat16 g_Q1h[(size_t)TOT * EMB], g_Q1l[(size_t)TOT * EMB];
__device__ __nv_bfloat16 g_Q2h[(size_t)TOT * EMB], g_Q2l[(size_t)TOT * EMB];
__device__ __nv_bfloat16 g_Kh[(size_t)TOT * EMB],  g_Kl[(size_t)TOT * EMB];
__device__ __nv_bfloat16 g_Vh[(size_t)TOT * EMB],  g_Vl[(size_t)TOT * EMB];
__device__ int g_perm[TOT];
__device__ int g_n1;
__device__ __align__(16) __nv_bfloat16 g_zero16[8];   // zero-initialized

// ---------------------------------------------------------------------------
__device__ __forceinline__ uint32_t pack_bf16(float x, float y) {
    __nv_bfloat162 h = __floats2bfloat162_rn(x, y);
    return *reinterpret_cast<uint32_t*>(&h);
}
__device__ __forceinline__ float bf16_hi_f(float x) {
    return __bfloat162float(__float2bfloat16_rn(x));
}
__device__ __forceinline__ void mma_bf16(float* c, const uint32_t* a, const uint32_t* b) {
    asm volatile(
        "mma.sync.aligned.m16n8k16.row.col.f32.bf16.bf16.f32 "
        "{%0,%1,%2,%3}, {%4,%5,%6,%7}, {%8,%9}, {%0,%1,%2,%3};"
        : "+f"(c[0]), "+f"(c[1]), "+f"(c[2]), "+f"(c[3])
        : "r"(a[0]), "r"(a[1]), "r"(a[2]), "r"(a[3]), "r"(b[0]), "r"(b[1]));
}
__device__ __forceinline__ void ldm_x4(uint32_t* r, uint32_t a) {
    asm volatile("ldmatrix.sync.aligned.m8n8.x4.shared.b16 {%0,%1,%2,%3}, [%4];"
        : "=r"(r[0]), "=r"(r[1]), "=r"(r[2]), "=r"(r[3]) : "r"(a));
}
__device__ __forceinline__ void ldm_x4t(uint32_t* r, uint32_t a) {
    asm volatile("ldmatrix.sync.aligned.m8n8.x4.trans.shared.b16 {%0,%1,%2,%3}, [%4];"
        : "=r"(r[0]), "=r"(r[1]), "=r"(r[2]), "=r"(r[3]) : "r"(a));
}
__device__ __forceinline__ uint32_t smaddr(const void* p) {
    return (uint32_t)__cvta_generic_to_shared(p);
}
#define CPA16(dst, src) \
    asm volatile("cp.async.cg.shared.global [%0], [%1], 16;" :: "r"(dst), "l"(src))
#define CPA_COMMIT() asm volatile("cp.async.commit_group;")
#define CPA_WAIT(n)  asm volatile("cp.async.wait_group %0;" :: "n"(n))

__device__ __forceinline__ void cvt_store4(float4 v, __nv_bfloat16* hi, __nv_bfloat16* lo) {
    float hx = bf16_hi_f(v.x), hy = bf16_hi_f(v.y);
    float hz = bf16_hi_f(v.z), hw = bf16_hi_f(v.w);
    *reinterpret_cast<uint2*>(hi) = make_uint2(pack_bf16(v.x, v.y), pack_bf16(v.z, v.w));
    *reinterpret_cast<uint2*>(lo) = make_uint2(pack_bf16(v.x - hx, v.y - hy),
                                               pack_bf16(v.z - hz, v.w - hw));
}

// ---------------------------------------------------------------------------
// Stable partition of rows by label (lab=1 first). One block, deterministic.
// ---------------------------------------------------------------------------
__global__ __launch_bounds__(512) void partition_kernel(
    const int* __restrict__ labels, int* __restrict__ perm, int* __restrict__ n1out)
{
    __shared__ int s[512];
    __shared__ int tot1;
    int tid = threadIdx.x;
    int base = tid * 32;
    int c = 0;
#pragma unroll
    for (int i = 0; i < 32; i++) c += labels[base + i];
    s[tid] = c;
    __syncthreads();
    for (int off = 1; off < 512; off <<= 1) {
        int v = (tid >= off) ? s[tid - off] : 0;
        __syncthreads();
        if (tid >= off) s[tid] += v;
        __syncthreads();
    }
    int incl = s[tid];
    int excl = incl - c;
    if (tid == 511) { tot1 = incl; *n1out = incl; }
    __syncthreads();
    int p1 = excl;
    int p0 = tot1 + base - excl;
    for (int i = 0; i < 32; i++) {
        int g = base + i;
        if (labels[g]) perm[p1++] = g;
        else           perm[p0++] = g;
    }
}

// ---------------------------------------------------------------------------
// Gather: emits half planes [g,512] and query planes [g,512]
// ---------------------------------------------------------------------------
__global__ __launch_bounds__(128) void gather_kernel(
    const int* __restrict__ item_inputs, const int* __restrict__ skill_inputs,
    const int* __restrict__ item_ids, const int* __restrict__ skill_ids,
    const float* __restrict__ item_emb, const float* __restrict__ skill_emb,
    __nv_bfloat16* __restrict__ Hh, __nv_bfloat16* __restrict__ Hl,
    __nv_bfloat16* __restrict__ QRh, __nv_bfloat16* __restrict__ QRl)
{
    int g = blockIdx.x;
    int t = threadIdx.x;
    size_t hb = (size_t)g * 512, qb = (size_t)g * 512;
    if (t < 64) {
        const float4* ie = reinterpret_cast<const float4*>(item_emb + (size_t)item_inputs[g] * 256);
        cvt_store4(ie[t], Hh + hb + t * 4, Hl + hb + t * 4);
        const float4* qe = reinterpret_cast<const float4*>(item_emb + (size_t)item_ids[g] * 256);
        cvt_store4(qe[t], QRh + qb + t * 4, QRl + qb + t * 4);
    } else {
        int u = t - 64;
        const float4* se = reinterpret_cast<const float4*>(skill_emb + (size_t)skill_inputs[g] * 256);
        cvt_store4(se[u], Hh + hb + 256 + u * 4, Hl + hb + 256 + u * 4);
        const float4* qs = reinterpret_cast<const float4*>(skill_emb + (size_t)skill_ids[g] * 256);
        cvt_store4(qs[u], QRh + qb + 256 + u * 4, QRl + qb + 256 + u * 4);
    }
}

// ---------------------------------------------------------------------------
// Unified weight transpose (+ bf16 hi/lo split), 8 z-slices.
// z=0,1: W_in [1024,512] y-halves. z=2..7: QKV [512,512].
// ---------------------------------------------------------------------------
struct TrAll {
    const float* src[8];
    __nv_bfloat16* dhi[8];
    __nv_bfloat16* dlo[8];
    int K[8];
    int yoff[8];
};
__global__ __launch_bounds__(256) void transpose_all_kernel(TrAll a)
{
    __shared__ float t[32][33];
    int z = blockIdx.z;
    const float* src = a.src[z];
    __nv_bfloat16* dhi = a.dhi[z];
    __nv_bfloat16* dlo = a.dlo[z];
    int K = a.K[z];
    int bx = blockIdx.x * 32;
    int by = (blockIdx.y + a.yoff[z]) * 32;
    int x = threadIdx.x & 31, y0 = threadIdx.x >> 5;
#pragma unroll
    for (int j = 0; j < 32; j += 8)
        t[y0 + j][x] = src[(size_t)(by + y0 + j) * 512 + bx + x];
    __syncthreads();
#pragma unroll
    for (int j = 0; j < 32; j += 8) {
        float v = t[x][y0 + j];
        float h = bf16_hi_f(v);
        size_t idx = (size_t)(bx + y0 + j) * K + by + x;
        dhi[idx] = __float2bfloat16_rn(v);
        dlo[idx] = __float2bfloat16_rn(v - h);
    }
}

// ---------------------------------------------------------------------------
// GEMM shared machinery: 128x128 tile, 8 warps, K-chunk 32, double buffer.
// ---------------------------------------------------------------------------
#define RSTR 40
#define PLANE_B (128 * RSTR * 2)
#define STAGE_B (4 * PLANE_B)
#define GEMM_SMEM (2 * STAGE_B)

__device__ __forceinline__ void gemm_chunk_pipe(
    uint32_t cur, float (&acc)[4][4][4], int wm, int wn,
    int lm, int kq, int nb, int kb2, bool tail_sync)
{
    uint32_t a_u = cur;
    uint32_t b_u = cur + 2 * PLANE_B;

    uint32_t bfh[2][4][2], bfl[2][4][2];
#pragma unroll
    for (int s = 0; s < 2; s++)
#pragma unroll
        for (int jp = 0; jp < 2; jp++) {
            uint32_t off = (uint32_t)((wn + jp * 16 + nb) * RSTR + s * 16 + kb2) * 2;
            uint32_t r[4];
            ldm_x4(r, b_u + off);
            bfh[s][jp * 2][0] = r[0]; bfh[s][jp * 2][1] = r[1];
            bfh[s][jp * 2 + 1][0] = r[2]; bfh[s][jp * 2 + 1][1] = r[3];
            ldm_x4(r, b_u + PLANE_B + off);
            bfl[s][jp * 2][0] = r[0]; bfl[s][jp * 2][1] = r[1];
            bfl[s][jp * 2 + 1][0] = r[2]; bfl[s][jp * 2 + 1][1] = r[3];
        }

    uint32_t ah[2][4], al[2][4];
    {
        uint32_t off0 = (uint32_t)((wm + lm) * RSTR + kq) * 2;
        ldm_x4(ah[0], a_u + off0);
        ldm_x4(al[0], a_u + PLANE_B + off0);
    }
#pragma unroll
    for (int t = 0; t < 8; t++) {
        const int s = t >> 2, i = t & 3;
        const int cb = t & 1;
        if (t < 7) {
            const int tn = t + 1, sn = tn >> 2, in = tn & 3;
            uint32_t offn = (uint32_t)((wm + in * 16 + lm) * RSTR + sn * 16 + kq) * 2;
            ldm_x4(ah[cb ^ 1], a_u + offn);
            ldm_x4(al[cb ^ 1], a_u + PLANE_B + offn);
        } else if (tail_sync) {
            CPA_WAIT(0);
            __syncthreads();
        }
#pragma unroll
        for (int j = 0; j < 4; j++) mma_bf16(acc[i][j], ah[cb], bfh[s][j]);
#pragma unroll
        for (int j = 0; j < 4; j++) mma_bf16(acc[i][j], al[cb], bfh[s][j]);
#pragma unroll
        for (int j = 0; j < 4; j++) mma_bf16(acc[i][j], ah[cb], bfl[s][j]);
    }
}

// ---------------------------------------------------------------------------
// MLP GEMM over partitioned rows (K=512 per pass, weight-half selected).
// ---------------------------------------------------------------------------
__global__ __launch_bounds__(256, 2)
void gemm_mlp_kernel(const __nv_bfloat16* __restrict__ Hh,
                     const __nv_bfloat16* __restrict__ Hl,
                     const __nv_bfloat16* __restrict__ Wh,
                     const __nv_bfloat16* __restrict__ Wl,
                     const float* __restrict__ bias,
                     __nv_bfloat16* __restrict__ Xh,
                     __nv_bfloat16* __restrict__ Xl,
                     const int* __restrict__ perm,
                     const int* __restrict__ n1p)
{
    extern __shared__ __align__(16) char dsm[];
    int tid = threadIdx.x;
    int wid = tid >> 5, lane = tid & 31;
    int g = lane >> 2, t = lane & 3;
    int bm = blockIdx.y * 128, bn = blockIdx.x * 128;
    int wm = (wid & 1) * 64, wn = (wid >> 1) * 32;
    int lm = lane & 15, kq = (lane >> 4) << 3;
    int nb = (lane & 7) + ((lane >> 4) << 3);
    int kb2 = ((lane >> 3) & 1) * 8;

    int n1 = *n1p;
    int mode = (bm + 128 <= n1) ? 0 : ((bm >= n1) ? 1 : 2);
    int NC = (mode == 2) ? 32 : 16;

    int fr[2], fc[2];
#pragma unroll
    for (int i = 0; i < 2; i++) { int f = tid + i * 256; fr[i] = f >> 2; fc[i] = (f & 3) * 8; }

    const __nv_bfloat16* rAh[2];
    const __nv_bfloat16* rAl[2];
    bool is1[2];
#pragma unroll
    for (int i = 0; i < 2; i++) {
        int pos = bm + fr[i];
        int pr = perm[pos];
        rAh[i] = Hh + (size_t)pr * 512;
        rAl[i] = Hl + (size_t)pr * 512;
        is1[i] = pos < n1;
    }

    float acc[4][4][4];
#pragma unroll
    for (int i = 0; i < 4; i++)
#pragma unroll
        for (int j = 0; j < 4; j++)
#pragma unroll
            for (int r = 0; r < 4; r++) acc[i][j][r] = 0.f;

    auto load_stage = [&](uint32_t st, int ci) {
        int pass = (mode == 2) ? (ci >> 4) : mode;
        int k0 = (ci & 15) << 5;
        const __nv_bfloat16* Bh = Wh + (pass ? 512 : 0);
        const __nv_bfloat16* Bl = Wl + (pass ? 512 : 0);
#pragma unroll
        for (int i = 0; i < 2; i++) {
            uint32_t doff = (uint32_t)(fr[i] * RSTR + fc[i]) * 2;
            bool on = (mode != 2) || ((pass == 0) ? is1[i] : !is1[i]);
            const __nv_bfloat16* sah = on ? (rAh[i] + k0 + fc[i]) : g_zero16;
            const __nv_bfloat16* sal = on ? (rAl[i] + k0 + fc[i]) : g_zero16;
            CPA16(st + doff, sah);
            CPA16(st + PLANE_B + doff, sal);
            size_t gb = (size_t)(bn + fr[i]) * 1024 + k0 + fc[i];
            CPA16(st + 2 * PLANE_B + doff, Bh + gb);
            CPA16(st + 3 * PLANE_B + doff, Bl + gb);
        }
        CPA_COMMIT();
    };

    load_stage(smaddr(dsm), 0);
    CPA_WAIT(0);
    __syncthreads();

    for (int chunk = 0; chunk < NC; chunk++) {
        uint32_t cur = smaddr(dsm) + (chunk & 1) * STAGE_B;
        bool more = (chunk + 1 < NC);
        if (more)
            load_stage(smaddr(dsm) + ((chunk + 1) & 1) * STAGE_B, chunk + 1);
        gemm_chunk_pipe(cur, acc, wm, wn, lm, kq, nb, kb2, more);
    }

#pragma unroll
    for (int i = 0; i < 4; i++) {
        int pos0 = bm + wm + i * 16 + g;
        int orow0 = perm[pos0];
        int orow1 = perm[pos0 + 8];
#pragma unroll
        for (int j = 0; j < 4; j++) {
            int col = bn + wn + j * 8 + t * 2;
            float2 bv = *reinterpret_cast<const float2*>(bias + col);
            float v0 = fmaxf(acc[i][j][0] + bv.x, 0.f);
            float v1 = fmaxf(acc[i][j][1] + bv.y, 0.f);
            float v2 = fmaxf(acc[i][j][2] + bv.x, 0.f);
            float v3 = fmaxf(acc[i][j][3] + bv.y, 0.f);
            size_t i0 = (size_t)orow0 * 512 + col;
            size_t i1 = (size_t)orow1 * 512 + col;
            *reinterpret_cast<uint32_t*>(Xh + i0) = pack_bf16(v0, v1);
            *reinterpret_cast<uint32_t*>(Xl + i0) =
                pack_bf16(v0 - bf16_hi_f(v0), v1 - bf16_hi_f(v1));
            *reinterpret_cast<uint32_t*>(Xh + i1) = pack_bf16(v2, v3);
            *reinterpret_cast<uint32_t*>(Xl + i1) =
                pack_bf16(v2 - bf16_hi_f(v2), v3 - bf16_hi_f(v3));
        }
    }
}

// ---------------------------------------------------------------------------
// Fused projections: z selects problem (K=512), plane output.
// ---------------------------------------------------------------------------
struct QKVArgs {
    const __nv_bfloat16* Ah[4];
    const __nv_bfloat16* Al[4];
    const __nv_bfloat16* Bh[4];
    const __nv_bfloat16* Bl[4];
    const float* bias[4];
    __nv_bfloat16* Ch[4];
    __nv_bfloat16* Cl[4];
};
__global__ __launch_bounds__(256, 2)
void gemm_qkv_kernel(QKVArgs args)
{
    extern __shared__ __align__(16) char dsm[];
    const int K = 512;
    int z = blockIdx.z;
    const __nv_bfloat16* Ah = args.Ah[z];
    const __nv_bfloat16* Al = args.Al[z];
    const __nv_bfloat16* Bthi = args.Bh[z];
    const __nv_bfloat16* Btlo = args.Bl[z];
    const float* bias = args.bias[z];
    __nv_bfloat16* Chi = args.Ch[z];
    __nv_bfloat16* Clo = args.Cl[z];

    int tid = threadIdx.x;
    int wid = tid >> 5, lane = tid & 31;
    int g = lane >> 2, t = lane & 3;
    int bm = blockIdx.y * 128, bn = blockIdx.x * 128;
    int wm = (wid & 1) * 64, wn = (wid >> 1) * 32;
    const int NC = 16;
    int lm = lane & 15, kq = (lane >> 4) << 3;
    int nb = (lane & 7) + ((lane >> 4) << 3);
    int kb2 = ((lane >> 3) & 1) * 8;

    int fr[2], fc[2];
#pragma unroll
    for (int i = 0; i < 2; i++) { int f = tid + i * 256; fr[i] = f >> 2; fc[i] = (f & 3) * 8; }

    float acc[4][4][4];
#pragma unroll
    for (int i = 0; i < 4; i++)
#pragma unroll
        for (int j = 0; j < 4; j++)
#pragma unroll
            for (int r = 0; r < 4; r++) acc[i][j][r] = 0.f;

    auto load_stage = [&](uint32_t st, int k0) {
#pragma unroll
        for (int i = 0; i < 2; i++) {
            uint32_t doff = (uint32_t)(fr[i] * RSTR + fc[i]) * 2;
            size_t ga = (size_t)(bm + fr[i]) * K + k0 + fc[i];
            size_t gb = (size_t)(bn + fr[i]) * K + k0 + fc[i];
            CPA16(st + doff, Ah + ga);
            CPA16(st + PLANE_B + doff, Al + ga);
            CPA16(st + 2 * PLANE_B + doff, Bthi + gb);
            CPA16(st + 3 * PLANE_B + doff, Btlo + gb);
        }
        CPA_COMMIT();
    };

    load_stage(smaddr(dsm), 0);
    CPA_WAIT(0);
    __syncthreads();

    for (int chunk = 0; chunk < NC; chunk++) {
        uint32_t cur = smaddr(dsm) + (chunk & 1) * STAGE_B;
        bool more = (chunk + 1 < NC);
        if (more)
            load_stage(smaddr(dsm) + ((chunk + 1) & 1) * STAGE_B, (chunk + 1) << 5);
        gemm_chunk_pipe(cur, acc, wm, wn, lm, kq, nb, kb2, more);
    }

#pragma unroll
    for (int i = 0; i < 4; i++) {
        int row0 = bm + wm + i * 16 + g;
#pragma unroll
        for (int j = 0; j < 4; j++) {
            int col = bn + wn + j * 8 + t * 2;
            float2 bv = *reinterpret_cast<const float2*>(bias + col);
            float v0 = acc[i][j][0] + bv.x, v1 = acc[i][j][1] + bv.y;
            float v2 = acc[i][j][2] + bv.x, v3 = acc[i][j][3] + bv.y;
            size_t i0 = (size_t)row0 * 512 + col;
            size_t i1 = (size_t)(row0 + 8) * 512 + col;
            *reinterpret_cast<uint32_t*>(Chi + i0) = pack_bf16(v0, v1);
            *reinterpret_cast<uint32_t*>(Clo + i0) =
                pack_bf16(v0 - bf16_hi_f(v0), v1 - bf16_hi_f(v1));
            *reinterpret_cast<uint32_t*>(Chi + i1) = pack_bf16(v2, v3);
            *reinterpret_cast<uint32_t*>(Clo + i1) =
                pack_bf16(v2 - bf16_hi_f(v2), v3 - bf16_hi_f(v3));
        }
    }
}

// ---------------------------------------------------------------------------
// Flash attention: cp.async double-buffered K/V, Q frags in registers.
// CTA = balanced pair of q-tiles (3,0)/(2,1) -> 10 KV tiles each.
// OUT=0: write f32 Op + planes. OUT=1: Op += relu(result).
// ---------------------------------------------------------------------------
#define QS 72
#define FPL (64 * QS)
#define FSTG_B (4 * FPL * 2)
#define FL_SMEM (2 * FSTG_B)

template<int OUT>
__global__ __launch_bounds__(256, 2) void flash_bf16_kernel(
    const __nv_bfloat16* __restrict__ Qh, const __nv_bfloat16* __restrict__ Ql,
    const __nv_bfloat16* __restrict__ Kh, const __nv_bfloat16* __restrict__ Kl,
    const __nv_bfloat16* __restrict__ Vh, const __nv_bfloat16* __restrict__ Vl,
    float* __restrict__ Op,
    __nv_bfloat16* __restrict__ Ohp, __nv_bfloat16* __restrict__ Olp)
{
    extern __shared__ __align__(16) char fsm[];

    int tid = threadIdx.x;
    int wid = tid >> 5, lane = tid & 31;
    int g = lane >> 2, t = lane & 3;
    int qtx = blockIdx.x;
    int h = blockIdx.y, b = blockIdx.z;
    size_t kvoff = ((size_t)b * SEQ) * EMB + h * DHD;

    int rb = wid * 16;
    int lm = lane & 15, kq = (lane >> 4) << 3;
    int nbk = (lane & 7) + ((lane >> 4) << 3);
    int kb2 = ((lane >> 3) & 1) * 8;
    int kv = (lane & 7) + ((lane >> 3) & 1) * 8;
    int nv = (lane >> 4) << 3;

    int fr[2], fc[2];
#pragma unroll
    for (int i = 0; i < 2; i++) {
        int f = tid + i * 256;
        fr[i] = f >> 3; fc[i] = (f & 7) * 8;
    }

    for (int pass = 0; pass < 2; pass++) {
        int qt = (pass == 0) ? (3 - qtx) : qtx;
        size_t qoff = ((size_t)(b * SEQ + qt * 128)) * EMB + h * DHD;

        uint32_t qah[4][4], qal[4][4];
        {
            __nv_bfloat16* sQh = reinterpret_cast<__nv_bfloat16*>(fsm);
            __nv_bfloat16* sQl = sQh + 128 * QS;
#pragma unroll
            for (int i = 0; i < 4; i++) {
                int f = tid + i * 256;
                int r = f >> 3, c = (f & 7) * 8;
                *reinterpret_cast<uint4*>(sQh + r * QS + c) =
                    *reinterpret_cast<const uint4*>(Qh + qoff + (size_t)r * EMB + c);
                *reinterpret_cast<uint4*>(sQl + r * QS + c) =
                    *reinterpret_cast<const uint4*>(Ql + qoff + (size_t)r * EMB + c);
            }
            __syncthreads();
            uint32_t uQh = smaddr(sQh), uQl = smaddr(sQl);
#pragma unroll
            for (int kk = 0; kk < 4; kk++) {
                uint32_t qo = (uint32_t)((rb + lm) * QS + kk * 16 + kq) * 2;
                ldm_x4(qah[kk], uQh + qo);
                ldm_x4(qal[kk], uQl + qo);
            }
            __syncthreads();
        }

        int ktmax = qt * 2 + 1;
        int wmaxrow = qt * 128 + rb + 15;
        int row0g = qt * 128 + rb + g, row1g = row0g + 8;

        {
            uint32_t st = smaddr(fsm);
#pragma unroll
            for (int i = 0; i < 2; i++) {
                uint32_t doff = (uint32_t)(fr[i] * QS + fc[i]) * 2;
                size_t go = kvoff + (size_t)fr[i] * EMB + fc[i];
                CPA16(st + doff, Kh + go);
                CPA16(st + FPL * 2 + doff, Kl + go);
                CPA16(st + 2 * FPL * 2 + doff, Vh + go);
                CPA16(st + 3 * FPL * 2 + doff, Vl + go);
            }
            CPA_COMMIT();
        }

        float m0 = -INFINITY, m1 = -INFINITY, l0 = 0.f, l1 = 0.f;
        float acc[8][4];
#pragma unroll
        for (int j = 0; j < 8; j++)
#pragma unroll
            for (int r = 0; r < 4; r++) acc[j][r] = 0.f;

        for (int kt = 0; kt <= ktmax; kt++) {
            uint32_t cur = smaddr(fsm) + (kt & 1) * FSTG_B;
            bool more = (kt < ktmax);
            if (more) {
                uint32_t nxt = smaddr(fsm) + ((kt + 1) & 1) * FSTG_B;
                size_t ko = kvoff + (size_t)(kt + 1) * 64 * EMB;
#pragma unroll
                for (int i = 0; i < 2; i++) {
                    uint32_t doff = (uint32_t)(fr[i] * QS + fc[i]) * 2;
                    size_t go = ko + (size_t)fr[i] * EMB + fc[i];
                    CPA16(nxt + doff, Kh + go);
                    CPA16(nxt + FPL * 2 + doff, Kl + go);
                    CPA16(nxt + 2 * FPL * 2 + doff, Vh + go);
                    CPA16(nxt + 3 * FPL * 2 + doff, Vl + go);
                }
                CPA_COMMIT();
                CPA_WAIT(1);
            } else {
                CPA_WAIT(0);
            }
            __syncthreads();

            if (kt * 64 <= wmaxrow) {
                uint32_t uKh = cur, uKl = cur + FPL * 2;
                uint32_t uVh = cur + 2 * FPL * 2, uVl = cur + 3 * FPL * 2;

                float s[8][4];
#pragma unroll
                for (int j = 0; j < 8; j++)
#pragma unroll
                    for (int r = 0; r < 4; r++) s[j][r] = 0.f;
#pragma unroll
                for (int kk = 0; kk < 4; kk++) {
#pragma unroll
                    for (int jp = 0; jp < 4; jp++) {
                        uint32_t koff = (uint32_t)((jp * 16 + nbk) * QS + kk * 16 + kb2) * 2;
                        uint32_t rh[4], rl[4];
                        ldm_x4(rh, uKh + koff);
                        ldm_x4(rl, uKl + koff);
                        uint32_t b0[2] = { rh[0], rh[1] }, b1[2] = { rh[2], rh[3] };
                        uint32_t c0[2] = { rl[0], rl[1] }, c1[2] = { rl[2], rl[3] };
                        mma_bf16(s[2 * jp],     qah[kk], b0);
                        mma_bf16(s[2 * jp + 1], qah[kk], b1);
                        mma_bf16(s[2 * jp],     qal[kk], b0);
                        mma_bf16(s[2 * jp + 1], qal[kk], b1);
                        mma_bf16(s[2 * jp],     qah[kk], c0);
                        mma_bf16(s[2 * jp + 1], qah[kk], c1);
                    }
                }

                int colb = kt * 64 + t * 2;
#pragma unroll
                for (int j = 0; j < 8; j++) {
                    int c0 = colb + j * 8, c1 = c0 + 1;
                    s[j][0] = (c0 > row0g) ? -INFINITY : s[j][0] * ATTN_SCALE;
                    s[j][1] = (c1 > row0g) ? -INFINITY : s[j][1] * ATTN_SCALE;
                    s[j][2] = (c0 > row1g) ? -INFINITY : s[j][2] * ATTN_SCALE;
                    s[j][3] = (c1 > row1g) ? -INFINITY : s[j][3] * ATTN_SCALE;
                }

                float tm0 = -INFINITY, tm1 = -INFINITY;
#pragma unroll
                for (int j = 0; j < 8; j++) {
                    tm0 = fmaxf(tm0, fmaxf(s[j][0], s[j][1]));
                    tm1 = fmaxf(tm1, fmaxf(s[j][2], s[j][3]));
                }
                tm0 = fmaxf(tm0, __shfl_xor_sync(0xFFFFFFFFu, tm0, 1));
                tm0 = fmaxf(tm0, __shfl_xor_sync(0xFFFFFFFFu, tm0, 2));
                tm1 = fmaxf(tm1, __shfl_xor_sync(0xFFFFFFFFu, tm1, 1));
                tm1 = fmaxf(tm1, __shfl_xor_sync(0xFFFFFFFFu, tm1, 2));
                float m0n = fmaxf(m0, tm0), m1n = fmaxf(m1, tm1);
                float ms0 = fmaxf(m0n, -1e30f), ms1 = fmaxf(m1n, -1e30f);
                float alpha0 = __expf(m0 - ms0), alpha1 = __expf(m1 - ms1);
                m0 = m0n; m1 = m1n;
#pragma unroll
                for (int j = 0; j < 8; j++) {
                    acc[j][0] *= alpha0; acc[j][1] *= alpha0;
                    acc[j][2] *= alpha1; acc[j][3] *= alpha1;
                }

                float ps0 = 0.f, ps1 = 0.f;
#pragma unroll
                for (int kk = 0; kk < 4; kk++) {
                    int j0 = 2 * kk, j1 = 2 * kk + 1;
                    float p00 = __expf(s[j0][0] - ms0), p01 = __expf(s[j0][1] - ms0);
                    float p02 = __expf(s[j0][2] - ms1), p03 = __expf(s[j0][3] - ms1);
                    float p10 = __expf(s[j1][0] - ms0), p11 = __expf(s[j1][1] - ms0);
                    float p12 = __expf(s[j1][2] - ms1), p13 = __expf(s[j1][3] - ms1);
                    ps0 += p00 + p01 + p10 + p11;
                    ps1 += p02 + p03 + p12 + p13;
                    uint32_t pah[4], pal[4];
                    pah[0] = pack_bf16(p00, p01);
                    pah[1] = pack_bf16(p02, p03);
                    pah[2] = pack_bf16(p10, p11);
                    pah[3] = pack_bf16(p12, p13);
                    pal[0] = pack_bf16(p00 - bf16_hi_f(p00), p01 - bf16_hi_f(p01));
                    pal[1] = pack_bf16(p02 - bf16_hi_f(p02), p03 - bf16_hi_f(p03));
                    pal[2] = pack_bf16(p10 - bf16_hi_f(p10), p11 - bf16_hi_f(p11));
                    pal[3] = pack_bf16(p12 - bf16_hi_f(p12), p13 - bf16_hi_f(p13));
#pragma unroll
                    for (int jdp = 0; jdp < 4; jdp++) {
                        uint32_t voff = (uint32_t)((kk * 16 + kv) * QS + jdp * 16 + nv) * 2;
                        uint32_t rh[4], rl[4];
                        ldm_x4t(rh, uVh + voff);
                        ldm_x4t(rl, uVl + voff);
                        uint32_t b0[2] = { rh[0], rh[1] }, b1[2] = { rh[2], rh[3] };
                        uint32_t c0[2] = { rl[0], rl[1] }, c1[2] = { rl[2], rl[3] };
                        mma_bf16(acc[2 * jdp],     pah, b0);
                        mma_bf16(acc[2 * jdp + 1], pah, b1);
                        mma_bf16(acc[2 * jdp],     pal, b0);
                        mma_bf16(acc[2 * jdp + 1], pal, b1);
                        mma_bf16(acc[2 * jdp],     pah, c0);
                        mma_bf16(acc[2 * jdp + 1], pah, c1);
                    }
                }
                ps0 += __shfl_xor_sync(0xFFFFFFFFu, ps0, 1);
                ps0 += __shfl_xor_sync(0xFFFFFFFFu, ps0, 2);
                ps1 += __shfl_xor_sync(0xFFFFFFFFu, ps1, 1);
                ps1 += __shfl_xor_sync(0xFFFFFFFFu, ps1, 2);
                l0 = l0 * alpha0 + ps0;
                l1 = l1 * alpha1 + ps1;
            }
            __syncthreads();
        }

        float inv0 = 1.f / l0, inv1 = 1.f / l1;
#pragma unroll
        for (int jd = 0; jd < 8; jd++) {
            int c = jd * 8 + t * 2;
            size_t i0 = qoff + (size_t)(rb + g) * EMB + c;
            size_t i1 = qoff + (size_t)(rb + g + 8) * EMB + c;
            float o00 = acc[jd][0] * inv0, o01 = acc[jd][1] * inv0;
            float o10 = acc[jd][2] * inv1, o11 = acc[jd][3] * inv1;
            if (OUT == 0) {
                *reinterpret_cast<float2*>(Op + i0) = make_float2(o00, o01);
                *reinterpret_cast<float2*>(Op + i1) = make_float2(o10, o11);
                *reinterpret_cast<uint32_t*>(Ohp + i0) = pack_bf16(o00, o01);
                *reinterpret_cast<uint32_t*>(Olp + i0) =
                    pack_bf16(o00 - bf16_hi_f(o00), o01 - bf16_hi_f(o01));
                *reinterpret_cast<uint32_t*>(Ohp + i1) = pack_bf16(o10, o11);
                *reinterpret_cast<uint32_t*>(Olp + i1) =
                    pack_bf16(o10 - bf16_hi_f(o10), o11 - bf16_hi_f(o11));
            } else {
                float2 e0 = *reinterpret_cast<float2*>(Op + i0);
                float2 e1 = *reinterpret_cast<float2*>(Op + i1);
                *reinterpret_cast<float2*>(Op + i0) =
                    make_float2(e0.x + fmaxf(o00, 0.f), e0.y + fmaxf(o01, 0.f));
                *reinterpret_cast<float2*>(Op + i1) =
                    make_float2(e1.x + fmaxf(o10, 0.f), e1.y + fmaxf(o11, 0.f));
            }
        }
    }
}

// ---------------------------------------------------------------------------
__global__ __launch_bounds__(256) void out_proj_kernel(
    const float* __restrict__ out, const float* __restrict__ Wout,
    const float* __restrict__ bout, float* __restrict__ y)
{
    int g = blockIdx.x * 8 + (threadIdx.x >> 5);
    int lane = threadIdx.x & 31;
    const float4* o4 = reinterpret_cast<const float4*>(out + (size_t)g * EMB);
    const float4* w4 = reinterpret_cast<const float4*>(Wout);
    float s = 0.f;
#pragma unroll
    for (int i = 0; i < 4; i++) {
        float4 a = o4[lane + 32 * i];
        float4 b = w4[lane + 32 * i];
        s += a.x * b.x + a.y * b.y + a.z * b.z + a.w * b.w;
    }
#pragma unroll
    for (int off = 16; off > 0; off >>= 1)
        s += __shfl_xor_sync(0xFFFFFFFFu, s, off);
    if (lane == 0) y[g] = s + bout[0];
}

// ---------------------------------------------------------------------------
extern "C" void kernel_launch(void* const* d_in, const int* in_sizes, int n_in,
                              void* d_out, int out_size)
{
    const int*   item_inputs  = (const int*)d_in[0];
    const int*   skill_inputs = (const int*)d_in[1];
    const int*   label_inputs = (const int*)d_in[2];
    const int*   item_ids     = (const int*)d_in[3];
    const int*   skill_ids    = (const int*)d_in[4];
    const float* item_emb     = (const float*)d_in[5];
    const float* skill_emb    = (const float*)d_in[6];
    const float* W_in         = (const float*)d_in[7];
    const float* b_in         = (const float*)d_in[8];
    const float* Wq           = (const float*)d_in[9];
    const float* bq           = (const float*)d_in[10];
    const float* Wk           = (const float*)d_in[11];
    const float* bk           = (const float*)d_in[12];
    const float* Wv           = (const float*)d_in[13];
    const float* bv           = (const float*)d_in[14];
    const float* W_out        = (const float*)d_in[22];
    const float* b_out        = (const float*)d_in[23];
    float* y = (float*)d_out;

    float* outb;
    __nv_bfloat16 *w, *hh, *hl, *qrh, *qrl, *xh, *xl, *oh, *ol;
    __nv_bfloat16 *q1h, *q1l, *q2h, *q2l, *kh, *kl, *vh, *vl;
    int *perm, *n1;
    cudaGetSymbolAddress((void**)&outb, g_outb);
    cudaGetSymbolAddress((void**)&w,    g_W);
    cudaGetSymbolAddress((void**)&hh,   g_Hh);
    cudaGetSymbolAddress((void**)&hl,   g_Hl);
    cudaGetSymbolAddress((void**)&qrh,  g_QRh);
    cudaGetSymbolAddress((void**)&qrl,  g_QRl);
    cudaGetSymbolAddress((void**)&xh,   g_Xh);
    cudaGetSymbolAddress((void**)&xl,   g_Xl);
    cudaGetSymbolAddress((void**)&oh,   g_Oh);
    cudaGetSymbolAddress((void**)&ol,   g_Ol);
    cudaGetSymbolAddress((void**)&q1h,  g_Q1h);
    cudaGetSymbolAddress((void**)&q1l,  g_Q1l);
    cudaGetSymbolAddress((void**)&q2h,  g_Q2h);
    cudaGetSymbolAddress((void**)&q2l,  g_Q2l);
    cudaGetSymbolAddress((void**)&kh,   g_Kh);
    cudaGetSymbolAddress((void**)&kl,   g_Kl);
    cudaGetSymbolAddress((void**)&vh,   g_Vh);
    cudaGetSymbolAddress((void**)&vl,   g_Vl);
    cudaGetSymbolAddress((void**)&perm, g_perm);
    cudaGetSymbolAddress((void**)&n1,   g_n1);

    cudaFuncSetAttribute(flash_bf16_kernel<0>,
                         cudaFuncAttributeMaxDynamicSharedMemorySize, FL_SMEM);
    cudaFuncSetAttribute(flash_bf16_kernel<1>,
                         cudaFuncAttributeMaxDynamicSharedMemorySize, FL_SMEM);
    cudaFuncSetAttribute(gemm_mlp_kernel,
                         cudaFuncAttributeMaxDynamicSharedMemorySize, GEMM_SMEM);
    cudaFuncSetAttribute(gemm_qkv_kernel,
                         cudaFuncAttributeMaxDynamicSharedMemorySize, GEMM_SMEM);

    __nv_bfloat16* win_hi = w;
    __nv_bfloat16* win_lo = w + 512 * 1024;
    __nv_bfloat16* qkv_hi[2][3];
    __nv_bfloat16* qkv_lo[2][3];
    {
        __nv_bfloat16* p = w + 2 * 512 * 1024;
        for (int l = 0; l < 2; l++)
            for (int m = 0; m < 3; m++) {
                qkv_hi[l][m] = p; p += 512 * 512;
                qkv_lo[l][m] = p; p += 512 * 512;
            }
    }

    // 0: partition
    partition_kernel<<<1, 512>>>(label_inputs, perm, n1);
    // 1: gather
    gather_kernel<<<TOT, 128>>>(item_inputs, skill_inputs,
                                item_ids, skill_ids, item_emb, skill_emb,
                                hh, hl, qrh, qrl);
    // 2: all transposes, one homogeneous launch (8 z-slices)
    {
        TrAll ta;
        ta.src[0] = W_in; ta.dhi[0] = win_hi; ta.dlo[0] = win_lo; ta.K[0] = 1024; ta.yoff[0] = 0;
        ta.src[1] = W_in; ta.dhi[1] = win_hi; ta.dlo[1] = win_lo; ta.K[1] = 1024; ta.yoff[1] = 16;
        const float* srcs[3] = { Wq, Wk, Wv };
        for (int l = 0; l < 2; l++)
            for (int m = 0; m < 3; m++) {
                int zi = 2 + l * 3 + m;
                ta.src[zi] = srcs[m] + (size_t)l * 512 * 512;
                ta.dhi[zi] = qkv_hi[l][m];
                ta.dlo[zi] = qkv_lo[l][m];
                ta.K[zi] = 512;
                ta.yoff[zi] = 0;
            }
        transpose_all_kernel<<<dim3(16, 16, 8), 256>>>(ta);
    }
    // 3: MLP (partitioned rows, K=512/pass)
    gemm_mlp_kernel<<<dim3(4, 128), 256, GEMM_SMEM>>>(
        hh, hl, win_hi, win_lo, b_in, xh, xl, perm, n1);
    // 4: fused Q1,K1,V1,Q2
    {
        QKVArgs qa;
        qa.Ah[0] = qrh; qa.Al[0] = qrl;
        qa.Ah[1] = xh;  qa.Al[1] = xl;
        qa.Ah[2] = xh;  qa.Al[2] = xl;
        qa.Ah[3] = qrh; qa.Al[3] = qrl;
        qa.Bh[0] = qkv_hi[0][0]; qa.Bl[0] = qkv_lo[0][0];
        qa.Bh[1] = qkv_hi[0][1]; qa.Bl[1] = qkv_lo[0][1];
        qa.Bh[2] = qkv_hi[0][2]; qa.Bl[2] = qkv_lo[0][2];
        qa.Bh[3] = qkv_hi[1][0]; qa.Bl[3] = qkv_lo[1][0];
        qa.bias[0] = bq; qa.bias[1] = bk; qa.bias[2] = bv; qa.bias[3] = bq + EMB;
        qa.Ch[0] = q1h; qa.Cl[0] = q1l;
        qa.Ch[1] = kh;  qa.Cl[1] = kl;
        qa.Ch[2] = vh;  qa.Cl[2] = vl;
        qa.Ch[3] = q2h; qa.Cl[3] = q2l;
        gemm_qkv_kernel<<<dim3(4, 128, 4), 256, GEMM_SMEM>>>(qa);
    }
    // 5: flash layer 1
    flash_bf16_kernel<0><<<dim3(2, NH, Bsz), 256, FL_SMEM>>>(
        q1h, q1l, kh, kl, vh, vl, outb, oh, ol);
    // 6: fused K2,V2
    {
        QKVArgs qa;
        qa.Ah[0] = oh; qa.Al[0] = ol;
        qa.Ah[1] = oh; qa.Al[1] = ol;
        qa.Ah[2] = oh; qa.Al[2] = ol;
        qa.Ah[3] = oh; qa.Al[3] = ol;
        qa.Bh[0] = qkv_hi[1][1]; qa.Bl[0] = qkv_lo[1][1];
        qa.Bh[1] = qkv_hi[1][2]; qa.Bl[1] = qkv_lo[1][2];
        qa.Bh[2] = qkv_hi[1][1]; qa.Bl[2] = qkv_lo[1][1];
        qa.Bh[3] = qkv_hi[1][2]; qa.Bl[3] = qkv_lo[1][2];
        qa.bias[0] = bk + EMB; qa.bias[1] = bv + EMB;
        qa.bias[2] = bk + EMB; qa.bias[3] = bv + EMB;
        qa.Ch[0] = kh; qa.Cl[0] = kl;
        qa.Ch[1] = vh; qa.Cl[1] = vl;
        qa.Ch[2] = kh; qa.Cl[2] = kl;
        qa.Ch[3] = vh; qa.Cl[3] = vl;
        gemm_qkv_kernel<<<dim3(4, 128, 2), 256, GEMM_SMEM>>>(qa);
    }
    // 7: flash layer 2 (residual add)
    flash_bf16_kernel<1><<<dim3(2, NH, Bsz), 256, FL_SMEM>>>(
        q2h, q2l, kh, kl, vh, vl, outb, nullptr, nullptr);
    // 8: output projection
    out_proj_kernel<<<TOT / 8, 256>>>(outb, W_out, b_out, y);
}

// round 14
// speedup vs baseline: 1.0678x; 1.0446x over previous
#include <cuda_runtime.h>
#include <cuda_bf16.h>
#include <cstdint>

// ---------------------------------------------------------------------------
// TSAKT: gather -> ReLU MLP -> 2x causal MHA -> output proj.
// glo/ts biases are key-constant pre-mask => softmax-shift-invariant => dropped.
// R14 = R13 kernels (byte-identical) + stream-fork overlap:
//   s2: partition -> transposes -> Q1,Q2        (forked via events)
//   d : gather -> MLP -> K1,V1 -> flash1 -> K2,V2 -> flash2 -> out_proj
// ---------------------------------------------------------------------------

#define Bsz 32
#define SEQ 512
#define EMB 512
#define NH  8
#define DHD 64
#define TOT (Bsz * SEQ)
#define ATTN_SCALE 0.125f

// ---- device scratch ---------------------------------------------------------
__device__ float g_outb [(size_t)TOT * EMB];
__device__ __nv_bfloat16 g_W[2 * 512 * 1024 + 12 * 512 * 512];
__device__ __nv_bfloat16 g_Hh[(size_t)TOT * 512],  g_Hl[(size_t)TOT * 512];
__device__ __nv_bfloat16 g_QRh[(size_t)TOT * EMB], g_QRl[(size_t)TOT * EMB];
__device__ __nv_bfloat16 g_Xh[(size_t)TOT * EMB],  g_Xl[(size_t)TOT * EMB];
__device__ __nv_bfloat16 g_Oh[(size_t)TOT * EMB],  g_Ol[(size_t)TOT * EMB];
__device__ __nv_bfloat16 g_Q1h[(size_t)TOT * EMB], g_Q1l[(size_t)TOT * EMB];
__device__ __nv_bfloat16 g_Q2h[(size_t)TOT * EMB], g_Q2l[(size_t)TOT * EMB];
__device__ __nv_bfloat16 g_Kh[(size_t)TOT * EMB],  g_Kl[(size_t)TOT * EMB];
__device__ __nv_bfloat16 g_Vh[(size_t)TOT * EMB],  g_Vl[(size_t)TOT * EMB];
__device__ int g_perm[TOT];
__device__ int g_n1;
__device__ __align__(16) __nv_bfloat16 g_zero16[8];   // zero-initialized

// ---------------------------------------------------------------------------
__device__ __forceinline__ uint32_t pack_bf16(float x, float y) {
    __nv_bfloat162 h = __floats2bfloat162_rn(x, y);
    return *reinterpret_cast<uint32_t*>(&h);
}
__device__ __forceinline__ float bf16_hi_f(float x) {
    return __bfloat162float(__float2bfloat16_rn(x));
}
__device__ __forceinline__ void mma_bf16(float* c, const uint32_t* a, const uint32_t* b) {
    asm volatile(
        "mma.sync.aligned.m16n8k16.row.col.f32.bf16.bf16.f32 "
        "{%0,%1,%2,%3}, {%4,%5,%6,%7}, {%8,%9}, {%0,%1,%2,%3};"
        : "+f"(c[0]), "+f"(c[1]), "+f"(c[2]), "+f"(c[3])
        : "r"(a[0]), "r"(a[1]), "r"(a[2]), "r"(a[3]), "r"(b[0]), "r"(b[1]));
}
__device__ __forceinline__ void ldm_x4(uint32_t* r, uint32_t a) {
    asm volatile("ldmatrix.sync.aligned.m8n8.x4.shared.b16 {%0,%1,%2,%3}, [%4];"
        : "=r"(r[0]), "=r"(r[1]), "=r"(r[2]), "=r"(r[3]) : "r"(a));
}
__device__ __forceinline__ void ldm_x4t(uint32_t* r, uint32_t a) {
    asm volatile("ldmatrix.sync.aligned.m8n8.x4.trans.shared.b16 {%0,%1,%2,%3}, [%4];"
        : "=r"(r[0]), "=r"(r[1]), "=r"(r[2]), "=r"(r[3]) : "r"(a));
}
__device__ __forceinline__ uint32_t smaddr(const void* p) {
    return (uint32_t)__cvta_generic_to_shared(p);
}
#define CPA16(dst, src) \
    asm volatile("cp.async.cg.shared.global [%0], [%1], 16;" :: "r"(dst), "l"(src))
#define CPA_COMMIT() asm volatile("cp.async.commit_group;")
#define CPA_WAIT(n)  asm volatile("cp.async.wait_group %0;" :: "n"(n))

__device__ __forceinline__ void cvt_store4(float4 v, __nv_bfloat16* hi, __nv_bfloat16* lo) {
    float hx = bf16_hi_f(v.x), hy = bf16_hi_f(v.y);
    float hz = bf16_hi_f(v.z), hw = bf16_hi_f(v.w);
    *reinterpret_cast<uint2*>(hi) = make_uint2(pack_bf16(v.x, v.y), pack_bf16(v.z, v.w));
    *reinterpret_cast<uint2*>(lo) = make_uint2(pack_bf16(v.x - hx, v.y - hy),
                                               pack_bf16(v.z - hz, v.w - hw));
}

// ---------------------------------------------------------------------------
// Stable partition of rows by label (lab=1 first). One block, deterministic.
// ---------------------------------------------------------------------------
__global__ __launch_bounds__(512) void partition_kernel(
    const int* __restrict__ labels, int* __restrict__ perm, int* __restrict__ n1out)
{
    __shared__ int s[512];
    __shared__ int tot1;
    int tid = threadIdx.x;
    int base = tid * 32;
    int c = 0;
#pragma unroll
    for (int i = 0; i < 32; i++) c += labels[base + i];
    s[tid] = c;
    __syncthreads();
    for (int off = 1; off < 512; off <<= 1) {
        int v = (tid >= off) ? s[tid - off] : 0;
        __syncthreads();
        if (tid >= off) s[tid] += v;
        __syncthreads();
    }
    int incl = s[tid];
    int excl = incl - c;
    if (tid == 511) { tot1 = incl; *n1out = incl; }
    __syncthreads();
    int p1 = excl;
    int p0 = tot1 + base - excl;
    for (int i = 0; i < 32; i++) {
        int g = base + i;
        if (labels[g]) perm[p1++] = g;
        else           perm[p0++] = g;
    }
}

// ---------------------------------------------------------------------------
// Gather: emits half planes [g,512] and query planes [g,512]
// ---------------------------------------------------------------------------
__global__ __launch_bounds__(128) void gather_kernel(
    const int* __restrict__ item_inputs, const int* __restrict__ skill_inputs,
    const int* __restrict__ item_ids, const int* __restrict__ skill_ids,
    const float* __restrict__ item_emb, const float* __restrict__ skill_emb,
    __nv_bfloat16* __restrict__ Hh, __nv_bfloat16* __restrict__ Hl,
    __nv_bfloat16* __restrict__ QRh, __nv_bfloat16* __restrict__ QRl)
{
    int g = blockIdx.x;
    int t = threadIdx.x;
    size_t hb = (size_t)g * 512, qb = (size_t)g * 512;
    if (t < 64) {
        const float4* ie = reinterpret_cast<const float4*>(item_emb + (size_t)item_inputs[g] * 256);
        cvt_store4(ie[t], Hh + hb + t * 4, Hl + hb + t * 4);
        const float4* qe = reinterpret_cast<const float4*>(item_emb + (size_t)item_ids[g] * 256);
        cvt_store4(qe[t], QRh + qb + t * 4, QRl + qb + t * 4);
    } else {
        int u = t - 64;
        const float4* se = reinterpret_cast<const float4*>(skill_emb + (size_t)skill_inputs[g] * 256);
        cvt_store4(se[u], Hh + hb + 256 + u * 4, Hl + hb + 256 + u * 4);
        const float4* qs = reinterpret_cast<const float4*>(skill_emb + (size_t)skill_ids[g] * 256);
        cvt_store4(qs[u], QRh + qb + 256 + u * 4, QRl + qb + 256 + u * 4);
    }
}

// ---------------------------------------------------------------------------
// Unified weight transpose (+ bf16 hi/lo split), 8 z-slices.
// ---------------------------------------------------------------------------
struct TrAll {
    const float* src[8];
    __nv_bfloat16* dhi[8];
    __nv_bfloat16* dlo[8];
    int K[8];
    int yoff[8];
};
__global__ __launch_bounds__(256) void transpose_all_kernel(TrAll a)
{
    __shared__ float t[32][33];
    int z = blockIdx.z;
    const float* src = a.src[z];
    __nv_bfloat16* dhi = a.dhi[z];
    __nv_bfloat16* dlo = a.dlo[z];
    int K = a.K[z];
    int bx = blockIdx.x * 32;
    int by = (blockIdx.y + a.yoff[z]) * 32;
    int x = threadIdx.x & 31, y0 = threadIdx.x >> 5;
#pragma unroll
    for (int j = 0; j < 32; j += 8)
        t[y0 + j][x] = src[(size_t)(by + y0 + j) * 512 + bx + x];
    __syncthreads();
#pragma unroll
    for (int j = 0; j < 32; j += 8) {
        float v = t[x][y0 + j];
        float h = bf16_hi_f(v);
        size_t idx = (size_t)(bx + y0 + j) * K + by + x;
        dhi[idx] = __float2bfloat16_rn(v);
        dlo[idx] = __float2bfloat16_rn(v - h);
    }
}

// ---------------------------------------------------------------------------
// GEMM shared machinery: 128x128 tile, 8 warps, K-chunk 32, double buffer.
// ---------------------------------------------------------------------------
#define RSTR 40
#define PLANE_B (128 * RSTR * 2)
#define STAGE_B (4 * PLANE_B)
#define GEMM_SMEM (2 * STAGE_B)

__device__ __forceinline__ void gemm_chunk_pipe(
    uint32_t cur, float (&acc)[4][4][4], int wm, int wn,
    int lm, int kq, int nb, int kb2, bool tail_sync)
{
    uint32_t a_u = cur;
    uint32_t b_u = cur + 2 * PLANE_B;

    uint32_t bfh[2][4][2], bfl[2][4][2];
#pragma unroll
    for (int s = 0; s < 2; s++)
#pragma unroll
        for (int jp = 0; jp < 2; jp++) {
            uint32_t off = (uint32_t)((wn + jp * 16 + nb) * RSTR + s * 16 + kb2) * 2;
            uint32_t r[4];
            ldm_x4(r, b_u + off);
            bfh[s][jp * 2][0] = r[0]; bfh[s][jp * 2][1] = r[1];
            bfh[s][jp * 2 + 1][0] = r[2]; bfh[s][jp * 2 + 1][1] = r[3];
            ldm_x4(r, b_u + PLANE_B + off);
            bfl[s][jp * 2][0] = r[0]; bfl[s][jp * 2][1] = r[1];
            bfl[s][jp * 2 + 1][0] = r[2]; bfl[s][jp * 2 + 1][1] = r[3];
        }

    uint32_t ah[2][4], al[2][4];
    {
        uint32_t off0 = (uint32_t)((wm + lm) * RSTR + kq) * 2;
        ldm_x4(ah[0], a_u + off0);
        ldm_x4(al[0], a_u + PLANE_B + off0);
    }
#pragma unroll
    for (int t = 0; t < 8; t++) {
        const int s = t >> 2, i = t & 3;
        const int cb = t & 1;
        if (t < 7) {
            const int tn = t + 1, sn = tn >> 2, in = tn & 3;
            uint32_t offn = (uint32_t)((wm + in * 16 + lm) * RSTR + sn * 16 + kq) * 2;
            ldm_x4(ah[cb ^ 1], a_u + offn);
            ldm_x4(al[cb ^ 1], a_u + PLANE_B + offn);
        } else if (tail_sync) {
            CPA_WAIT(0);
            __syncthreads();
        }
#pragma unroll
        for (int j = 0; j < 4; j++) mma_bf16(acc[i][j], ah[cb], bfh[s][j]);
#pragma unroll
        for (int j = 0; j < 4; j++) mma_bf16(acc[i][j], al[cb], bfh[s][j]);
#pragma unroll
        for (int j = 0; j < 4; j++) mma_bf16(acc[i][j], ah[cb], bfl[s][j]);
    }
}

// ---------------------------------------------------------------------------
// MLP GEMM over partitioned rows (K=512 per pass, weight-half selected).
// ---------------------------------------------------------------------------
__global__ __launch_bounds__(256, 2)
void gemm_mlp_kernel(const __nv_bfloat16* __restrict__ Hh,
                     const __nv_bfloat16* __restrict__ Hl,
                     const __nv_bfloat16* __restrict__ Wh,
                     const __nv_bfloat16* __restrict__ Wl,
                     const float* __restrict__ bias,
                     __nv_bfloat16* __restrict__ Xh,
                     __nv_bfloat16* __restrict__ Xl,
                     const int* __restrict__ perm,
                     const int* __restrict__ n1p)
{
    extern __shared__ __align__(16) char dsm[];
    int tid = threadIdx.x;
    int wid = tid >> 5, lane = tid & 31;
    int g = lane >> 2, t = lane & 3;
    int bm = blockIdx.y * 128, bn = blockIdx.x * 128;
    int wm = (wid & 1) * 64, wn = (wid >> 1) * 32;
    int lm = lane & 15, kq = (lane >> 4) << 3;
    int nb = (lane & 7) + ((lane >> 4) << 3);
    int kb2 = ((lane >> 3) & 1) * 8;

    int n1 = *n1p;
    int mode = (bm + 128 <= n1) ? 0 : ((bm >= n1) ? 1 : 2);
    int NC = (mode == 2) ? 32 : 16;

    int fr[2], fc[2];
#pragma unroll
    for (int i = 0; i < 2; i++) { int f = tid + i * 256; fr[i] = f >> 2; fc[i] = (f & 3) * 8; }

    const __nv_bfloat16* rAh[2];
    const __nv_bfloat16* rAl[2];
    bool is1[2];
#pragma unroll
    for (int i = 0; i < 2; i++) {
        int pos = bm + fr[i];
        int pr = perm[pos];
        rAh[i] = Hh + (size_t)pr * 512;
        rAl[i] = Hl + (size_t)pr * 512;
        is1[i] = pos < n1;
    }

    float acc[4][4][4];
#pragma unroll
    for (int i = 0; i < 4; i++)
#pragma unroll
        for (int j = 0; j < 4; j++)
#pragma unroll
            for (int r = 0; r < 4; r++) acc[i][j][r] = 0.f;

    auto load_stage = [&](uint32_t st, int ci) {
        int pass = (mode == 2) ? (ci >> 4) : mode;
        int k0 = (ci & 15) << 5;
        const __nv_bfloat16* Bh = Wh + (pass ? 512 : 0);
        const __nv_bfloat16* Bl = Wl + (pass ? 512 : 0);
#pragma unroll
        for (int i = 0; i < 2; i++) {
            uint32_t doff = (uint32_t)(fr[i] * RSTR + fc[i]) * 2;
            bool on = (mode != 2) || ((pass == 0) ? is1[i] : !is1[i]);
            const __nv_bfloat16* sah = on ? (rAh[i] + k0 + fc[i]) : g_zero16;
            const __nv_bfloat16* sal = on ? (rAl[i] + k0 + fc[i]) : g_zero16;
            CPA16(st + doff, sah);
            CPA16(st + PLANE_B + doff, sal);
            size_t gb = (size_t)(bn + fr[i]) * 1024 + k0 + fc[i];
            CPA16(st + 2 * PLANE_B + doff, Bh + gb);
            CPA16(st + 3 * PLANE_B + doff, Bl + gb);
        }
        CPA_COMMIT();
    };

    load_stage(smaddr(dsm), 0);
    CPA_WAIT(0);
    __syncthreads();

    for (int chunk = 0; chunk < NC; chunk++) {
        uint32_t cur = smaddr(dsm) + (chunk & 1) * STAGE_B;
        bool more = (chunk + 1 < NC);
        if (more)
            load_stage(smaddr(dsm) + ((chunk + 1) & 1) * STAGE_B, chunk + 1);
        gemm_chunk_pipe(cur, acc, wm, wn, lm, kq, nb, kb2, more);
    }

#pragma unroll
    for (int i = 0; i < 4; i++) {
        int pos0 = bm + wm + i * 16 + g;
        int orow0 = perm[pos0];
        int orow1 = perm[pos0 + 8];
#pragma unroll
        for (int j = 0; j < 4; j++) {
            int col = bn + wn + j * 8 + t * 2;
            float2 bv = *reinterpret_cast<const float2*>(bias + col);
            float v0 = fmaxf(acc[i][j][0] + bv.x, 0.f);
            float v1 = fmaxf(acc[i][j][1] + bv.y, 0.f);
            float v2 = fmaxf(acc[i][j][2] + bv.x, 0.f);
            float v3 = fmaxf(acc[i][j][3] + bv.y, 0.f);
            size_t i0 = (size_t)orow0 * 512 + col;
            size_t i1 = (size_t)orow1 * 512 + col;
            *reinterpret_cast<uint32_t*>(Xh + i0) = pack_bf16(v0, v1);
            *reinterpret_cast<uint32_t*>(Xl + i0) =
                pack_bf16(v0 - bf16_hi_f(v0), v1 - bf16_hi_f(v1));
            *reinterpret_cast<uint32_t*>(Xh + i1) = pack_bf16(v2, v3);
            *reinterpret_cast<uint32_t*>(Xl + i1) =
                pack_bf16(v2 - bf16_hi_f(v2), v3 - bf16_hi_f(v3));
        }
    }
}

// ---------------------------------------------------------------------------
// Fused projections: z selects problem (K=512), plane output.
// ---------------------------------------------------------------------------
struct QKVArgs {
    const __nv_bfloat16* Ah[4];
    const __nv_bfloat16* Al[4];
    const __nv_bfloat16* Bh[4];
    const __nv_bfloat16* Bl[4];
    const float* bias[4];
    __nv_bfloat16* Ch[4];
    __nv_bfloat16* Cl[4];
};
__global__ __launch_bounds__(256, 2)
void gemm_qkv_kernel(QKVArgs args)
{
    extern __shared__ __align__(16) char dsm[];
    const int K = 512;
    int z = blockIdx.z;
    const __nv_bfloat16* Ah = args.Ah[z];
    const __nv_bfloat16* Al = args.Al[z];
    const __nv_bfloat16* Bthi = args.Bh[z];
    const __nv_bfloat16* Btlo = args.Bl[z];
    const float* bias = args.bias[z];
    __nv_bfloat16* Chi = args.Ch[z];
    __nv_bfloat16* Clo = args.Cl[z];

    int tid = threadIdx.x;
    int wid = tid >> 5, lane = tid & 31;
    int g = lane >> 2, t = lane & 3;
    int bm = blockIdx.y * 128, bn = blockIdx.x * 128;
    int wm = (wid & 1) * 64, wn = (wid >> 1) * 32;
    const int NC = 16;
    int lm = lane & 15, kq = (lane >> 4) << 3;
    int nb = (lane & 7) + ((lane >> 4) << 3);
    int kb2 = ((lane >> 3) & 1) * 8;

    int fr[2], fc[2];
#pragma unroll
    for (int i = 0; i < 2; i++) { int f = tid + i * 256; fr[i] = f >> 2; fc[i] = (f & 3) * 8; }

    float acc[4][4][4];
#pragma unroll
    for (int i = 0; i < 4; i++)
#pragma unroll
        for (int j = 0; j < 4; j++)
#pragma unroll
            for (int r = 0; r < 4; r++) acc[i][j][r] = 0.f;

    auto load_stage = [&](uint32_t st, int k0) {
#pragma unroll
        for (int i = 0; i < 2; i++) {
            uint32_t doff = (uint32_t)(fr[i] * RSTR + fc[i]) * 2;
            size_t ga = (size_t)(bm + fr[i]) * K + k0 + fc[i];
            size_t gb = (size_t)(bn + fr[i]) * K + k0 + fc[i];
            CPA16(st + doff, Ah + ga);
            CPA16(st + PLANE_B + doff, Al + ga);
            CPA16(st + 2 * PLANE_B + doff, Bthi + gb);
            CPA16(st + 3 * PLANE_B + doff, Btlo + gb);
        }
        CPA_COMMIT();
    };

    load_stage(smaddr(dsm), 0);
    CPA_WAIT(0);
    __syncthreads();

    for (int chunk = 0; chunk < NC; chunk++) {
        uint32_t cur = smaddr(dsm) + (chunk & 1) * STAGE_B;
        bool more = (chunk + 1 < NC);
        if (more)
            load_stage(smaddr(dsm) + ((chunk + 1) & 1) * STAGE_B, (chunk + 1) << 5);
        gemm_chunk_pipe(cur, acc, wm, wn, lm, kq, nb, kb2, more);
    }

#pragma unroll
    for (int i = 0; i < 4; i++) {
        int row0 = bm + wm + i * 16 + g;
#pragma unroll
        for (int j = 0; j < 4; j++) {
            int col = bn + wn + j * 8 + t * 2;
            float2 bv = *reinterpret_cast<const float2*>(bias + col);
            float v0 = acc[i][j][0] + bv.x, v1 = acc[i][j][1] + bv.y;
            float v2 = acc[i][j][2] + bv.x, v3 = acc[i][j][3] + bv.y;
            size_t i0 = (size_t)row0 * 512 + col;
            size_t i1 = (size_t)(row0 + 8) * 512 + col;
            *reinterpret_cast<uint32_t*>(Chi + i0) = pack_bf16(v0, v1);
            *reinterpret_cast<uint32_t*>(Clo + i0) =
                pack_bf16(v0 - bf16_hi_f(v0), v1 - bf16_hi_f(v1));
            *reinterpret_cast<uint32_t*>(Chi + i1) = pack_bf16(v2, v3);
            *reinterpret_cast<uint32_t*>(Clo + i1) =
                pack_bf16(v2 - bf16_hi_f(v2), v3 - bf16_hi_f(v3));
        }
    }
}

// ---------------------------------------------------------------------------
// Flash attention: cp.async double-buffered K/V, Q frags in registers.
// CTA = balanced pair of q-tiles (3,0)/(2,1) -> 10 KV tiles each.
// OUT=0: write f32 Op + planes. OUT=1: Op += relu(result).
// ---------------------------------------------------------------------------
#define QS 72
#define FPL (64 * QS)
#define FSTG_B (4 * FPL * 2)
#define FL_SMEM (2 * FSTG_B)

template<int OUT>
__global__ __launch_bounds__(256, 2) void flash_bf16_kernel(
    const __nv_bfloat16* __restrict__ Qh, const __nv_bfloat16* __restrict__ Ql,
    const __nv_bfloat16* __restrict__ Kh, const __nv_bfloat16* __restrict__ Kl,
    const __nv_bfloat16* __restrict__ Vh, const __nv_bfloat16* __restrict__ Vl,
    float* __restrict__ Op,
    __nv_bfloat16* __restrict__ Ohp, __nv_bfloat16* __restrict__ Olp)
{
    extern __shared__ __align__(16) char fsm[];

    int tid = threadIdx.x;
    int wid = tid >> 5, lane = tid & 31;
    int g = lane >> 2, t = lane & 3;
    int qtx = blockIdx.x;
    int h = blockIdx.y, b = blockIdx.z;
    size_t kvoff = ((size_t)b * SEQ) * EMB + h * DHD;

    int rb = wid * 16;
    int lm = lane & 15, kq = (lane >> 4) << 3;
    int nbk = (lane & 7) + ((lane >> 4) << 3);
    int kb2 = ((lane >> 3) & 1) * 8;
    int kv = (lane & 7) + ((lane >> 3) & 1) * 8;
    int nv = (lane >> 4) << 3;

    int fr[2], fc[2];
#pragma unroll
    for (int i = 0; i < 2; i++) {
        int f = tid + i * 256;
        fr[i] = f >> 3; fc[i] = (f & 7) * 8;
    }

    for (int pass = 0; pass < 2; pass++) {
        int qt = (pass == 0) ? (3 - qtx) : qtx;
        size_t qoff = ((size_t)(b * SEQ + qt * 128)) * EMB + h * DHD;

        uint32_t qah[4][4], qal[4][4];
        {
            __nv_bfloat16* sQh = reinterpret_cast<__nv_bfloat16*>(fsm);
            __nv_bfloat16* sQl = sQh + 128 * QS;
#pragma unroll
            for (int i = 0; i < 4; i++) {
                int f = tid + i * 256;
                int r = f >> 3, c = (f & 7) * 8;
                *reinterpret_cast<uint4*>(sQh + r * QS + c) =
                    *reinterpret_cast<const uint4*>(Qh + qoff + (size_t)r * EMB + c);
                *reinterpret_cast<uint4*>(sQl + r * QS + c) =
                    *reinterpret_cast<const uint4*>(Ql + qoff + (size_t)r * EMB + c);
            }
            __syncthreads();
            uint32_t uQh = smaddr(sQh), uQl = smaddr(sQl);
#pragma unroll
            for (int kk = 0; kk < 4; kk++) {
                uint32_t qo = (uint32_t)((rb + lm) * QS + kk * 16 + kq) * 2;
                ldm_x4(qah[kk], uQh + qo);
                ldm_x4(qal[kk], uQl + qo);
            }
            __syncthreads();
        }

        int ktmax = qt * 2 + 1;
        int wmaxrow = qt * 128 + rb + 15;
        int row0g = qt * 128 + rb + g, row1g = row0g + 8;

        {
            uint32_t st = smaddr(fsm);
#pragma unroll
            for (int i = 0; i < 2; i++) {
                uint32_t doff = (uint32_t)(fr[i] * QS + fc[i]) * 2;
                size_t go = kvoff + (size_t)fr[i] * EMB + fc[i];
                CPA16(st + doff, Kh + go);
                CPA16(st + FPL * 2 + doff, Kl + go);
                CPA16(st + 2 * FPL * 2 + doff, Vh + go);
                CPA16(st + 3 * FPL * 2 + doff, Vl + go);
            }
            CPA_COMMIT();
        }

        float m0 = -INFINITY, m1 = -INFINITY, l0 = 0.f, l1 = 0.f;
        float acc[8][4];
#pragma unroll
        for (int j = 0; j < 8; j++)
#pragma unroll
            for (int r = 0; r < 4; r++) acc[j][r] = 0.f;

        for (int kt = 0; kt <= ktmax; kt++) {
            uint32_t cur = smaddr(fsm) + (kt & 1) * FSTG_B;
            bool more = (kt < ktmax);
            if (more) {
                uint32_t nxt = smaddr(fsm) + ((kt + 1) & 1) * FSTG_B;
                size_t ko = kvoff + (size_t)(kt + 1) * 64 * EMB;
#pragma unroll
                for (int i = 0; i < 2; i++) {
                    uint32_t doff = (uint32_t)(fr[i] * QS + fc[i]) * 2;
                    size_t go = ko + (size_t)fr[i] * EMB + fc[i];
                    CPA16(nxt + doff, Kh + go);
                    CPA16(nxt + FPL * 2 + doff, Kl + go);
                    CPA16(nxt + 2 * FPL * 2 + doff, Vh + go);
                    CPA16(nxt + 3 * FPL * 2 + doff, Vl + go);
                }
                CPA_COMMIT();
                CPA_WAIT(1);
            } else {
                CPA_WAIT(0);
            }
            __syncthreads();

            if (kt * 64 <= wmaxrow) {
                uint32_t uKh = cur, uKl = cur + FPL * 2;
                uint32_t uVh = cur + 2 * FPL * 2, uVl = cur + 3 * FPL * 2;

                float s[8][4];
#pragma unroll
                for (int j = 0; j < 8; j++)
#pragma unroll
                    for (int r = 0; r < 4; r++) s[j][r] = 0.f;
#pragma unroll
                for (int kk = 0; kk < 4; kk++) {
#pragma unroll
                    for (int jp = 0; jp < 4; jp++) {
                        uint32_t koff = (uint32_t)((jp * 16 + nbk) * QS + kk * 16 + kb2) * 2;
                        uint32_t rh[4], rl[4];
                        ldm_x4(rh, uKh + koff);
                        ldm_x4(rl, uKl + koff);
                        uint32_t b0[2] = { rh[0], rh[1] }, b1[2] = { rh[2], rh[3] };
                        uint32_t c0[2] = { rl[0], rl[1] }, c1[2] = { rl[2], rl[3] };
                        mma_bf16(s[2 * jp],     qah[kk], b0);
                        mma_bf16(s[2 * jp + 1], qah[kk], b1);
                        mma_bf16(s[2 * jp],     qal[kk], b0);
                        mma_bf16(s[2 * jp + 1], qal[kk], b1);
                        mma_bf16(s[2 * jp],     qah[kk], c0);
                        mma_bf16(s[2 * jp + 1], qah[kk], c1);
                    }
                }

                int colb = kt * 64 + t * 2;
#pragma unroll
                for (int j = 0; j < 8; j++) {
                    int c0 = colb + j * 8, c1 = c0 + 1;
                    s[j][0] = (c0 > row0g) ? -INFINITY : s[j][0] * ATTN_SCALE;
                    s[j][1] = (c1 > row0g) ? -INFINITY : s[j][1] * ATTN_SCALE;
                    s[j][2] = (c0 > row1g) ? -INFINITY : s[j][2] * ATTN_SCALE;
                    s[j][3] = (c1 > row1g) ? -INFINITY : s[j][3] * ATTN_SCALE;
                }

                float tm0 = -INFINITY, tm1 = -INFINITY;
#pragma unroll
                for (int j = 0; j < 8; j++) {
                    tm0 = fmaxf(tm0, fmaxf(s[j][0], s[j][1]));
                    tm1 = fmaxf(tm1, fmaxf(s[j][2], s[j][3]));
                }
                tm0 = fmaxf(tm0, __shfl_xor_sync(0xFFFFFFFFu, tm0, 1));
                tm0 = fmaxf(tm0, __shfl_xor_sync(0xFFFFFFFFu, tm0, 2));
                tm1 = fmaxf(tm1, __shfl_xor_sync(0xFFFFFFFFu, tm1, 1));
                tm1 = fmaxf(tm1, __shfl_xor_sync(0xFFFFFFFFu, tm1, 2));
                float m0n = fmaxf(m0, tm0), m1n = fmaxf(m1, tm1);
                float ms0 = fmaxf(m0n, -1e30f), ms1 = fmaxf(m1n, -1e30f);
                float alpha0 = __expf(m0 - ms0), alpha1 = __expf(m1 - ms1);
                m0 = m0n; m1 = m1n;
#pragma unroll
                for (int j = 0; j < 8; j++) {
                    acc[j][0] *= alpha0; acc[j][1] *= alpha0;
                    acc[j][2] *= alpha1; acc[j][3] *= alpha1;
                }

                float ps0 = 0.f, ps1 = 0.f;
#pragma unroll
                for (int kk = 0; kk < 4; kk++) {
                    int j0 = 2 * kk, j1 = 2 * kk + 1;
                    float p00 = __expf(s[j0][0] - ms0), p01 = __expf(s[j0][1] - ms0);
                    float p02 = __expf(s[j0][2] - ms1), p03 = __expf(s[j0][3] - ms1);
                    float p10 = __expf(s[j1][0] - ms0), p11 = __expf(s[j1][1] - ms0);
                    float p12 = __expf(s[j1][2] - ms1), p13 = __expf(s[j1][3] - ms1);
                    ps0 += p00 + p01 + p10 + p11;
                    ps1 += p02 + p03 + p12 + p13;
                    uint32_t pah[4], pal[4];
                    pah[0] = pack_bf16(p00, p01);
                    pah[1] = pack_bf16(p02, p03);
                    pah[2] = pack_bf16(p10, p11);
                    pah[3] = pack_bf16(p12, p13);
                    pal[0] = pack_bf16(p00 - bf16_hi_f(p00), p01 - bf16_hi_f(p01));
                    pal[1] = pack_bf16(p02 - bf16_hi_f(p02), p03 - bf16_hi_f(p03));
                    pal[2] = pack_bf16(p10 - bf16_hi_f(p10), p11 - bf16_hi_f(p11));
                    pal[3] = pack_bf16(p12 - bf16_hi_f(p12), p13 - bf16_hi_f(p13));
#pragma unroll
                    for (int jdp = 0; jdp < 4; jdp++) {
                        uint32_t voff = (uint32_t)((kk * 16 + kv) * QS + jdp * 16 + nv) * 2;
                        uint32_t rh[4], rl[4];
                        ldm_x4t(rh, uVh + voff);
                        ldm_x4t(rl, uVl + voff);
                        uint32_t b0[2] = { rh[0], rh[1] }, b1[2] = { rh[2], rh[3] };
                        uint32_t c0[2] = { rl[0], rl[1] }, c1[2] = { rl[2], rl[3] };
                        mma_bf16(acc[2 * jdp],     pah, b0);
                        mma_bf16(acc[2 * jdp + 1], pah, b1);
                        mma_bf16(acc[2 * jdp],     pal, b0);
                        mma_bf16(acc[2 * jdp + 1], pal, b1);
                        mma_bf16(acc[2 * jdp],     pah, c0);
                        mma_bf16(acc[2 * jdp + 1], pah, c1);
                    }
                }
                ps0 += __shfl_xor_sync(0xFFFFFFFFu, ps0, 1);
                ps0 += __shfl_xor_sync(0xFFFFFFFFu, ps0, 2);
                ps1 += __shfl_xor_sync(0xFFFFFFFFu, ps1, 1);
                ps1 += __shfl_xor_sync(0xFFFFFFFFu, ps1, 2);
                l0 = l0 * alpha0 + ps0;
                l1 = l1 * alpha1 + ps1;
            }
            __syncthreads();
        }

        float inv0 = 1.f / l0, inv1 = 1.f / l1;
#pragma unroll
        for (int jd = 0; jd < 8; jd++) {
            int c = jd * 8 + t * 2;
            size_t i0 = qoff + (size_t)(rb + g) * EMB + c;
            size_t i1 = qoff + (size_t)(rb + g + 8) * EMB + c;
            float o00 = acc[jd][0] * inv0, o01 = acc[jd][1] * inv0;
            float o10 = acc[jd][2] * inv1, o11 = acc[jd][3] * inv1;
            if (OUT == 0) {
                *reinterpret_cast<float2*>(Op + i0) = make_float2(o00, o01);
                *reinterpret_cast<float2*>(Op + i1) = make_float2(o10, o11);
                *reinterpret_cast<uint32_t*>(Ohp + i0) = pack_bf16(o00, o01);
                *reinterpret_cast<uint32_t*>(Olp + i0) =
                    pack_bf16(o00 - bf16_hi_f(o00), o01 - bf16_hi_f(o01));
                *reinterpret_cast<uint32_t*>(Ohp + i1) = pack_bf16(o10, o11);
                *reinterpret_cast<uint32_t*>(Olp + i1) =
                    pack_bf16(o10 - bf16_hi_f(o10), o11 - bf16_hi_f(o11));
            } else {
                float2 e0 = *reinterpret_cast<float2*>(Op + i0);
                float2 e1 = *reinterpret_cast<float2*>(Op + i1);
                *reinterpret_cast<float2*>(Op + i0) =
                    make_float2(e0.x + fmaxf(o00, 0.f), e0.y + fmaxf(o01, 0.f));
                *reinterpret_cast<float2*>(Op + i1) =
                    make_float2(e1.x + fmaxf(o10, 0.f), e1.y + fmaxf(o11, 0.f));
            }
        }
    }
}

// ---------------------------------------------------------------------------
__global__ __launch_bounds__(256) void out_proj_kernel(
    const float* __restrict__ out, const float* __restrict__ Wout,
    const float* __restrict__ bout, float* __restrict__ y)
{
    int g = blockIdx.x * 8 + (threadIdx.x >> 5);
    int lane = threadIdx.x & 31;
    const float4* o4 = reinterpret_cast<const float4*>(out + (size_t)g * EMB);
    const float4* w4 = reinterpret_cast<const float4*>(Wout);
    float s = 0.f;
#pragma unroll
    for (int i = 0; i < 4; i++) {
        float4 a = o4[lane + 32 * i];
        float4 b = w4[lane + 32 * i];
        s += a.x * b.x + a.y * b.y + a.z * b.z + a.w * b.w;
    }
#pragma unroll
    for (int off = 16; off > 0; off >>= 1)
        s += __shfl_xor_sync(0xFFFFFFFFu, s, off);
    if (lane == 0) y[g] = s + bout[0];
}

// ---------------------------------------------------------------------------
extern "C" void kernel_launch(void* const* d_in, const int* in_sizes, int n_in,
                              void* d_out, int out_size)
{
    const int*   item_inputs  = (const int*)d_in[0];
    const int*   skill_inputs = (const int*)d_in[1];
    const int*   label_inputs = (const int*)d_in[2];
    const int*   item_ids     = (const int*)d_in[3];
    const int*   skill_ids    = (const int*)d_in[4];
    const float* item_emb     = (const float*)d_in[5];
    const float* skill_emb    = (const float*)d_in[6];
    const float* W_in         = (const float*)d_in[7];
    const float* b_in         = (const float*)d_in[8];
    const float* Wq           = (const float*)d_in[9];
    const float* bq           = (const float*)d_in[10];
    const float* Wk           = (const float*)d_in[11];
    const float* bk           = (const float*)d_in[12];
    const float* Wv           = (const float*)d_in[13];
    const float* bv           = (const float*)d_in[14];
    const float* W_out        = (const float*)d_in[22];
    const float* b_out        = (const float*)d_in[23];
    float* y = (float*)d_out;

    float* outb;
    __nv_bfloat16 *w, *hh, *hl, *qrh, *qrl, *xh, *xl, *oh, *ol;
    __nv_bfloat16 *q1h, *q1l, *q2h, *q2l, *kh, *kl, *vh, *vl;
    int *perm, *n1;
    cudaGetSymbolAddress((void**)&outb, g_outb);
    cudaGetSymbolAddress((void**)&w,    g_W);
    cudaGetSymbolAddress((void**)&hh,   g_Hh);
    cudaGetSymbolAddress((void**)&hl,   g_Hl);
    cudaGetSymbolAddress((void**)&qrh,  g_QRh);
    cudaGetSymbolAddress((void**)&qrl,  g_QRl);
    cudaGetSymbolAddress((void**)&xh,   g_Xh);
    cudaGetSymbolAddress((void**)&xl,   g_Xl);
    cudaGetSymbolAddress((void**)&oh,   g_Oh);
    cudaGetSymbolAddress((void**)&ol,   g_Ol);
    cudaGetSymbolAddress((void**)&q1h,  g_Q1h);
    cudaGetSymbolAddress((void**)&q1l,  g_Q1l);
    cudaGetSymbolAddress((void**)&q2h,  g_Q2h);
    cudaGetSymbolAddress((void**)&q2l,  g_Q2l);
    cudaGetSymbolAddress((void**)&kh,   g_Kh);
    cudaGetSymbolAddress((void**)&kl,   g_Kl);
    cudaGetSymbolAddress((void**)&vh,   g_Vh);
    cudaGetSymbolAddress((void**)&vl,   g_Vl);
    cudaGetSymbolAddress((void**)&perm, g_perm);
    cudaGetSymbolAddress((void**)&n1,   g_n1);

    cudaFuncSetAttribute(flash_bf16_kernel<0>,
                         cudaFuncAttributeMaxDynamicSharedMemorySize, FL_SMEM);
    cudaFuncSetAttribute(flash_bf16_kernel<1>,
                         cudaFuncAttributeMaxDynamicSharedMemorySize, FL_SMEM);
    cudaFuncSetAttribute(gemm_mlp_kernel,
                         cudaFuncAttributeMaxDynamicSharedMemorySize, GEMM_SMEM);
    cudaFuncSetAttribute(gemm_qkv_kernel,
                         cudaFuncAttributeMaxDynamicSharedMemorySize, GEMM_SMEM);

    __nv_bfloat16* win_hi = w;
    __nv_bfloat16* win_lo = w + 512 * 1024;
    __nv_bfloat16* qkv_hi[2][3];
    __nv_bfloat16* qkv_lo[2][3];
    {
        __nv_bfloat16* p = w + 2 * 512 * 1024;
        for (int l = 0; l < 2; l++)
            for (int m = 0; m < 3; m++) {
                qkv_hi[l][m] = p; p += 512 * 512;
                qkv_lo[l][m] = p; p += 512 * 512;
            }
    }

    // ---- stream fork (graph-capturable; host objects leak, no device alloc) --
    cudaStream_t s2;
    cudaStreamCreateWithFlags(&s2, cudaStreamNonBlocking);
    cudaEvent_t e0, eG, eT, eQ;
    cudaEventCreateWithFlags(&e0, cudaEventDisableTiming);
    cudaEventCreateWithFlags(&eG, cudaEventDisableTiming);
    cudaEventCreateWithFlags(&eT, cudaEventDisableTiming);
    cudaEventCreateWithFlags(&eQ, cudaEventDisableTiming);

    // fork point
    cudaEventRecord(e0, 0);
    cudaStreamWaitEvent(s2, e0, 0);

    // ---- s2 branch: partition -> transposes -> (after gather) Q1,Q2 ----
    partition_kernel<<<1, 512, 0, s2>>>(label_inputs, perm, n1);
    {
        TrAll ta;
        ta.src[0] = W_in; ta.dhi[0] = win_hi; ta.dlo[0] = win_lo; ta.K[0] = 1024; ta.yoff[0] = 0;
        ta.src[1] = W_in; ta.dhi[1] = win_hi; ta.dlo[1] = win_lo; ta.K[1] = 1024; ta.yoff[1] = 16;
        const float* srcs[3] = { Wq, Wk, Wv };
        for (int l = 0; l < 2; l++)
            for (int m = 0; m < 3; m++) {
                int zi = 2 + l * 3 + m;
                ta.src[zi] = srcs[m] + (size_t)l * 512 * 512;
                ta.dhi[zi] = qkv_hi[l][m];
                ta.dlo[zi] = qkv_lo[l][m];
                ta.K[zi] = 512;
                ta.yoff[zi] = 0;
            }
        transpose_all_kernel<<<dim3(16, 16, 8), 256, 0, s2>>>(ta);
    }
    cudaEventRecord(eT, s2);

    // ---- default branch: gather ----
    gather_kernel<<<TOT, 128>>>(item_inputs, skill_inputs,
                                item_ids, skill_ids, item_emb, skill_emb,
                                hh, hl, qrh, qrl);
    cudaEventRecord(eG, 0);

    // s2: Q1,Q2 (needs gather + transpose)
    cudaStreamWaitEvent(s2, eG, 0);
    {
        QKVArgs qa;
        qa.Ah[0] = qrh; qa.Al[0] = qrl;
        qa.Ah[1] = qrh; qa.Al[1] = qrl;
        qa.Ah[2] = qrh; qa.Al[2] = qrl;
        qa.Ah[3] = qrh; qa.Al[3] = qrl;
        qa.Bh[0] = qkv_hi[0][0]; qa.Bl[0] = qkv_lo[0][0];
        qa.Bh[1] = qkv_hi[1][0]; qa.Bl[1] = qkv_lo[1][0];
        qa.Bh[2] = qkv_hi[0][0]; qa.Bl[2] = qkv_lo[0][0];
        qa.Bh[3] = qkv_hi[1][0]; qa.Bl[3] = qkv_lo[1][0];
        qa.bias[0] = bq; qa.bias[1] = bq + EMB;
        qa.bias[2] = bq; qa.bias[3] = bq + EMB;
        qa.Ch[0] = q1h; qa.Cl[0] = q1l;
        qa.Ch[1] = q2h; qa.Cl[1] = q2l;
        qa.Ch[2] = q1h; qa.Cl[2] = q1l;
        qa.Ch[3] = q2h; qa.Cl[3] = q2l;
        gemm_qkv_kernel<<<dim3(4, 128, 2), 256, GEMM_SMEM, s2>>>(qa);
    }
    cudaEventRecord(eQ, s2);

    // default: MLP (needs gather + transpose + partition)
    cudaStreamWaitEvent(0, eT, 0);
    gemm_mlp_kernel<<<dim3(4, 128), 256, GEMM_SMEM>>>(
        hh, hl, win_hi, win_lo, b_in, xh, xl, perm, n1);

    // default: K1,V1 (needs MLP)
    {
        QKVArgs qa;
        qa.Ah[0] = xh; qa.Al[0] = xl;
        qa.Ah[1] = xh; qa.Al[1] = xl;
        qa.Ah[2] = xh; qa.Al[2] = xl;
        qa.Ah[3] = xh; qa.Al[3] = xl;
        qa.Bh[0] = qkv_hi[0][1]; qa.Bl[0] = qkv_lo[0][1];
        qa.Bh[1] = qkv_hi[0][2]; qa.Bl[1] = qkv_lo[0][2];
        qa.Bh[2] = qkv_hi[0][1]; qa.Bl[2] = qkv_lo[0][1];
        qa.Bh[3] = qkv_hi[0][2]; qa.Bl[3] = qkv_lo[0][2];
        qa.bias[0] = bk; qa.bias[1] = bv;
        qa.bias[2] = bk; qa.bias[3] = bv;
        qa.Ch[0] = kh; qa.Cl[0] = kl;
        qa.Ch[1] = vh; qa.Cl[1] = vl;
        qa.Ch[2] = kh; qa.Cl[2] = kl;
        qa.Ch[3] = vh; qa.Cl[3] = vl;
        gemm_qkv_kernel<<<dim3(4, 128, 2), 256, GEMM_SMEM>>>(qa);
    }

    // join: flash1 needs Q1 (s2) + K1,V1 (default)
    cudaStreamWaitEvent(0, eQ, 0);
    flash_bf16_kernel<0><<<dim3(2, NH, Bsz), 256, FL_SMEM>>>(
        q1h, q1l, kh, kl, vh, vl, outb, oh, ol);

    // K2,V2 (needs flash1 planes)
    {
        QKVArgs qa;
        qa.Ah[0] = oh; qa.Al[0] = ol;
        qa.Ah[1] = oh; qa.Al[1] = ol;
        qa.Ah[2] = oh; qa.Al[2] = ol;
        qa.Ah[3] = oh; qa.Al[3] = ol;
        qa.Bh[0] = qkv_hi[1][1]; qa.Bl[0] = qkv_lo[1][1];
        qa.Bh[1] = qkv_hi[1][2]; qa.Bl[1] = qkv_lo[1][2];
        qa.Bh[2] = qkv_hi[1][1]; qa.Bl[2] = qkv_lo[1][1];
        qa.Bh[3] = qkv_hi[1][2]; qa.Bl[3] = qkv_lo[1][2];
        qa.bias[0] = bk + EMB; qa.bias[1] = bv + EMB;
        qa.bias[2] = bk + EMB; qa.bias[3] = bv + EMB;
        qa.Ch[0] = kh; qa.Cl[0] = kl;
        qa.Ch[1] = vh; qa.Cl[1] = vl;
        qa.Ch[2] = kh; qa.Cl[2] = kl;
        qa.Ch[3] = vh; qa.Cl[3] = vl;
        gemm_qkv_kernel<<<dim3(4, 128, 2), 256, GEMM_SMEM>>>(qa);
    }
    // flash layer 2 (residual add)
    flash_bf16_kernel<1><<<dim3(2, NH, Bsz), 256, FL_SMEM>>>(
        q2h, q2l, kh, kl, vh, vl, outb, nullptr, nullptr);
    // output projection
    out_proj_kernel<<<TOT / 8, 256>>>(outb, W_out, b_out, y);
}

// round 15
// speedup vs baseline: 1.0696x; 1.0017x over previous
#include <cuda_runtime.h>
#include <cuda_bf16.h>
#include <cstdint>

// ---------------------------------------------------------------------------
// TSAKT: gather -> ReLU MLP -> 2x causal MHA -> output proj.
// glo/ts biases are key-constant pre-mask => softmax-shift-invariant => dropped.
// R15 = R14 (stream-fork overlap) + per-q-tile flash CTAs, heavy-first
//       (finer scheduling granularity kills the 0.27-wave uniform tail).
// ---------------------------------------------------------------------------

#define Bsz 32
#define SEQ 512
#define EMB 512
#define NH  8
#define DHD 64
#define TOT (Bsz * SEQ)
#define ATTN_SCALE 0.125f

// ---- device scratch ---------------------------------------------------------
__device__ float g_outb [(size_t)TOT * EMB];
__device__ __nv_bfloat16 g_W[2 * 512 * 1024 + 12 * 512 * 512];
__device__ __nv_bfloat16 g_Hh[(size_t)TOT * 512],  g_Hl[(size_t)TOT * 512];
__device__ __nv_bfloat16 g_QRh[(size_t)TOT * EMB], g_QRl[(size_t)TOT * EMB];
__device__ __nv_bfloat16 g_Xh[(size_t)TOT * EMB],  g_Xl[(size_t)TOT * EMB];
__device__ __nv_bfloat16 g_Oh[(size_t)TOT * EMB],  g_Ol[(size_t)TOT * EMB];
__device__ __nv_bfloat16 g_Q1h[(size_t)TOT * EMB], g_Q1l[(size_t)TOT * EMB];
__device__ __nv_bfloat16 g_Q2h[(size_t)TOT * EMB], g_Q2l[(size_t)TOT * EMB];
__device__ __nv_bfloat16 g_Kh[(size_t)TOT * EMB],  g_Kl[(size_t)TOT * EMB];
__device__ __nv_bfloat16 g_Vh[(size_t)TOT * EMB],  g_Vl[(size_t)TOT * EMB];
__device__ int g_perm[TOT];
__device__ int g_n1;
__device__ __align__(16) __nv_bfloat16 g_zero16[8];   // zero-initialized

// ---------------------------------------------------------------------------
__device__ __forceinline__ uint32_t pack_bf16(float x, float y) {
    __nv_bfloat162 h = __floats2bfloat162_rn(x, y);
    return *reinterpret_cast<uint32_t*>(&h);
}
__device__ __forceinline__ float bf16_hi_f(float x) {
    return __bfloat162float(__float2bfloat16_rn(x));
}
__device__ __forceinline__ void mma_bf16(float* c, const uint32_t* a, const uint32_t* b) {
    asm volatile(
        "mma.sync.aligned.m16n8k16.row.col.f32.bf16.bf16.f32 "
        "{%0,%1,%2,%3}, {%4,%5,%6,%7}, {%8,%9}, {%0,%1,%2,%3};"
        : "+f"(c[0]), "+f"(c[1]), "+f"(c[2]), "+f"(c[3])
        : "r"(a[0]), "r"(a[1]), "r"(a[2]), "r"(a[3]), "r"(b[0]), "r"(b[1]));
}
__device__ __forceinline__ void ldm_x4(uint32_t* r, uint32_t a) {
    asm volatile("ldmatrix.sync.aligned.m8n8.x4.shared.b16 {%0,%1,%2,%3}, [%4];"
        : "=r"(r[0]), "=r"(r[1]), "=r"(r[2]), "=r"(r[3]) : "r"(a));
}
__device__ __forceinline__ void ldm_x4t(uint32_t* r, uint32_t a) {
    asm volatile("ldmatrix.sync.aligned.m8n8.x4.trans.shared.b16 {%0,%1,%2,%3}, [%4];"
        : "=r"(r[0]), "=r"(r[1]), "=r"(r[2]), "=r"(r[3]) : "r"(a));
}
__device__ __forceinline__ uint32_t smaddr(const void* p) {
    return (uint32_t)__cvta_generic_to_shared(p);
}
#define CPA16(dst, src) \
    asm volatile("cp.async.cg.shared.global [%0], [%1], 16;" :: "r"(dst), "l"(src))
#define CPA_COMMIT() asm volatile("cp.async.commit_group;")
#define CPA_WAIT(n)  asm volatile("cp.async.wait_group %0;" :: "n"(n))

__device__ __forceinline__ void cvt_store4(float4 v, __nv_bfloat16* hi, __nv_bfloat16* lo) {
    float hx = bf16_hi_f(v.x), hy = bf16_hi_f(v.y);
    float hz = bf16_hi_f(v.z), hw = bf16_hi_f(v.w);
    *reinterpret_cast<uint2*>(hi) = make_uint2(pack_bf16(v.x, v.y), pack_bf16(v.z, v.w));
    *reinterpret_cast<uint2*>(lo) = make_uint2(pack_bf16(v.x - hx, v.y - hy),
                                               pack_bf16(v.z - hz, v.w - hw));
}

// ---------------------------------------------------------------------------
// Stable partition of rows by label (lab=1 first). One block, deterministic.
// ---------------------------------------------------------------------------
__global__ __launch_bounds__(512) void partition_kernel(
    const int* __restrict__ labels, int* __restrict__ perm, int* __restrict__ n1out)
{
    __shared__ int s[512];
    __shared__ int tot1;
    int tid = threadIdx.x;
    int base = tid * 32;
    int c = 0;
#pragma unroll
    for (int i = 0; i < 32; i++) c += labels[base + i];
    s[tid] = c;
    __syncthreads();
    for (int off = 1; off < 512; off <<= 1) {
        int v = (tid >= off) ? s[tid - off] : 0;
        __syncthreads();
        if (tid >= off) s[tid] += v;
        __syncthreads();
    }
    int incl = s[tid];
    int excl = incl - c;
    if (tid == 511) { tot1 = incl; *n1out = incl; }
    __syncthreads();
    int p1 = excl;
    int p0 = tot1 + base - excl;
    for (int i = 0; i < 32; i++) {
        int g = base + i;
        if (labels[g]) perm[p1++] = g;
        else           perm[p0++] = g;
    }
}

// ---------------------------------------------------------------------------
// Gather: emits half planes [g,512] and query planes [g,512]
// ---------------------------------------------------------------------------
__global__ __launch_bounds__(128) void gather_kernel(
    const int* __restrict__ item_inputs, const int* __restrict__ skill_inputs,
    const int* __restrict__ item_ids, const int* __restrict__ skill_ids,
    const float* __restrict__ item_emb, const float* __restrict__ skill_emb,
    __nv_bfloat16* __restrict__ Hh, __nv_bfloat16* __restrict__ Hl,
    __nv_bfloat16* __restrict__ QRh, __nv_bfloat16* __restrict__ QRl)
{
    int g = blockIdx.x;
    int t = threadIdx.x;
    size_t hb = (size_t)g * 512, qb = (size_t)g * 512;
    if (t < 64) {
        const float4* ie = reinterpret_cast<const float4*>(item_emb + (size_t)item_inputs[g] * 256);
        cvt_store4(ie[t], Hh + hb + t * 4, Hl + hb + t * 4);
        const float4* qe = reinterpret_cast<const float4*>(item_emb + (size_t)item_ids[g] * 256);
        cvt_store4(qe[t], QRh + qb + t * 4, QRl + qb + t * 4);
    } else {
        int u = t - 64;
        const float4* se = reinterpret_cast<const float4*>(skill_emb + (size_t)skill_inputs[g] * 256);
        cvt_store4(se[u], Hh + hb + 256 + u * 4, Hl + hb + 256 + u * 4);
        const float4* qs = reinterpret_cast<const float4*>(skill_emb + (size_t)skill_ids[g] * 256);
        cvt_store4(qs[u], QRh + qb + 256 + u * 4, QRl + qb + 256 + u * 4);
    }
}

// ---------------------------------------------------------------------------
// Unified weight transpose (+ bf16 hi/lo split), 8 z-slices.
// ---------------------------------------------------------------------------
struct TrAll {
    const float* src[8];
    __nv_bfloat16* dhi[8];
    __nv_bfloat16* dlo[8];
    int K[8];
    int yoff[8];
};
__global__ __launch_bounds__(256) void transpose_all_kernel(TrAll a)
{
    __shared__ float t[32][33];
    int z = blockIdx.z;
    const float* src = a.src[z];
    __nv_bfloat16* dhi = a.dhi[z];
    __nv_bfloat16* dlo = a.dlo[z];
    int K = a.K[z];
    int bx = blockIdx.x * 32;
    int by = (blockIdx.y + a.yoff[z]) * 32;
    int x = threadIdx.x & 31, y0 = threadIdx.x >> 5;
#pragma unroll
    for (int j = 0; j < 32; j += 8)
        t[y0 + j][x] = src[(size_t)(by + y0 + j) * 512 + bx + x];
    __syncthreads();
#pragma unroll
    for (int j = 0; j < 32; j += 8) {
        float v = t[x][y0 + j];
        float h = bf16_hi_f(v);
        size_t idx = (size_t)(bx + y0 + j) * K + by + x;
        dhi[idx] = __float2bfloat16_rn(v);
        dlo[idx] = __float2bfloat16_rn(v - h);
    }
}

// ---------------------------------------------------------------------------
// GEMM shared machinery: 128x128 tile, 8 warps, K-chunk 32, double buffer.
// ---------------------------------------------------------------------------
#define RSTR 40
#define PLANE_B (128 * RSTR * 2)
#define STAGE_B (4 * PLANE_B)
#define GEMM_SMEM (2 * STAGE_B)

__device__ __forceinline__ void gemm_chunk_pipe(
    uint32_t cur, float (&acc)[4][4][4], int wm, int wn,
    int lm, int kq, int nb, int kb2, bool tail_sync)
{
    uint32_t a_u = cur;
    uint32_t b_u = cur + 2 * PLANE_B;

    uint32_t bfh[2][4][2], bfl[2][4][2];
#pragma unroll
    for (int s = 0; s < 2; s++)
#pragma unroll
        for (int jp = 0; jp < 2; jp++) {
            uint32_t off = (uint32_t)((wn + jp * 16 + nb) * RSTR + s * 16 + kb2) * 2;
            uint32_t r[4];
            ldm_x4(r, b_u + off);
            bfh[s][jp * 2][0] = r[0]; bfh[s][jp * 2][1] = r[1];
            bfh[s][jp * 2 + 1][0] = r[2]; bfh[s][jp * 2 + 1][1] = r[3];
            ldm_x4(r, b_u + PLANE_B + off);
            bfl[s][jp * 2][0] = r[0]; bfl[s][jp * 2][1] = r[1];
            bfl[s][jp * 2 + 1][0] = r[2]; bfl[s][jp * 2 + 1][1] = r[3];
        }

    uint32_t ah[2][4], al[2][4];
    {
        uint32_t off0 = (uint32_t)((wm + lm) * RSTR + kq) * 2;
        ldm_x4(ah[0], a_u + off0);
        ldm_x4(al[0], a_u + PLANE_B + off0);
    }
#pragma unroll
    for (int t = 0; t < 8; t++) {
        const int s = t >> 2, i = t & 3;
        const int cb = t & 1;
        if (t < 7) {
            const int tn = t + 1, sn = tn >> 2, in = tn & 3;
            uint32_t offn = (uint32_t)((wm + in * 16 + lm) * RSTR + sn * 16 + kq) * 2;
            ldm_x4(ah[cb ^ 1], a_u + offn);
            ldm_x4(al[cb ^ 1], a_u + PLANE_B + offn);
        } else if (tail_sync) {
            CPA_WAIT(0);
            __syncthreads();
        }
#pragma unroll
        for (int j = 0; j < 4; j++) mma_bf16(acc[i][j], ah[cb], bfh[s][j]);
#pragma unroll
        for (int j = 0; j < 4; j++) mma_bf16(acc[i][j], al[cb], bfh[s][j]);
#pragma unroll
        for (int j = 0; j < 4; j++) mma_bf16(acc[i][j], ah[cb], bfl[s][j]);
    }
}

// ---------------------------------------------------------------------------
// MLP GEMM over partitioned rows (K=512 per pass, weight-half selected).
// ---------------------------------------------------------------------------
__global__ __launch_bounds__(256, 2)
void gemm_mlp_kernel(const __nv_bfloat16* __restrict__ Hh,
                     const __nv_bfloat16* __restrict__ Hl,
                     const __nv_bfloat16* __restrict__ Wh,
                     const __nv_bfloat16* __restrict__ Wl,
                     const float* __restrict__ bias,
                     __nv_bfloat16* __restrict__ Xh,
                     __nv_bfloat16* __restrict__ Xl,
                     const int* __restrict__ perm,
                     const int* __restrict__ n1p)
{
    extern __shared__ __align__(16) char dsm[];
    int tid = threadIdx.x;
    int wid = tid >> 5, lane = tid & 31;
    int g = lane >> 2, t = lane & 3;
    int bm = blockIdx.y * 128, bn = blockIdx.x * 128;
    int wm = (wid & 1) * 64, wn = (wid >> 1) * 32;
    int lm = lane & 15, kq = (lane >> 4) << 3;
    int nb = (lane & 7) + ((lane >> 4) << 3);
    int kb2 = ((lane >> 3) & 1) * 8;

    int n1 = *n1p;
    int mode = (bm + 128 <= n1) ? 0 : ((bm >= n1) ? 1 : 2);
    int NC = (mode == 2) ? 32 : 16;

    int fr[2], fc[2];
#pragma unroll
    for (int i = 0; i < 2; i++) { int f = tid + i * 256; fr[i] = f >> 2; fc[i] = (f & 3) * 8; }

    const __nv_bfloat16* rAh[2];
    const __nv_bfloat16* rAl[2];
    bool is1[2];
#pragma unroll
    for (int i = 0; i < 2; i++) {
        int pos = bm + fr[i];
        int pr = perm[pos];
        rAh[i] = Hh + (size_t)pr * 512;
        rAl[i] = Hl + (size_t)pr * 512;
        is1[i] = pos < n1;
    }

    float acc[4][4][4];
#pragma unroll
    for (int i = 0; i < 4; i++)
#pragma unroll
        for (int j = 0; j < 4; j++)
#pragma unroll
            for (int r = 0; r < 4; r++) acc[i][j][r] = 0.f;

    auto load_stage = [&](uint32_t st, int ci) {
        int pass = (mode == 2) ? (ci >> 4) : mode;
        int k0 = (ci & 15) << 5;
        const __nv_bfloat16* Bh = Wh + (pass ? 512 : 0);
        const __nv_bfloat16* Bl = Wl + (pass ? 512 : 0);
#pragma unroll
        for (int i = 0; i < 2; i++) {
            uint32_t doff = (uint32_t)(fr[i] * RSTR + fc[i]) * 2;
            bool on = (mode != 2) || ((pass == 0) ? is1[i] : !is1[i]);
            const __nv_bfloat16* sah = on ? (rAh[i] + k0 + fc[i]) : g_zero16;
            const __nv_bfloat16* sal = on ? (rAl[i] + k0 + fc[i]) : g_zero16;
            CPA16(st + doff, sah);
            CPA16(st + PLANE_B + doff, sal);
            size_t gb = (size_t)(bn + fr[i]) * 1024 + k0 + fc[i];
            CPA16(st + 2 * PLANE_B + doff, Bh + gb);
            CPA16(st + 3 * PLANE_B + doff, Bl + gb);
        }
        CPA_COMMIT();
    };

    load_stage(smaddr(dsm), 0);
    CPA_WAIT(0);
    __syncthreads();

    for (int chunk = 0; chunk < NC; chunk++) {
        uint32_t cur = smaddr(dsm) + (chunk & 1) * STAGE_B;
        bool more = (chunk + 1 < NC);
        if (more)
            load_stage(smaddr(dsm) + ((chunk + 1) & 1) * STAGE_B, chunk + 1);
        gemm_chunk_pipe(cur, acc, wm, wn, lm, kq, nb, kb2, more);
    }

#pragma unroll
    for (int i = 0; i < 4; i++) {
        int pos0 = bm + wm + i * 16 + g;
        int orow0 = perm[pos0];
        int orow1 = perm[pos0 + 8];
#pragma unroll
        for (int j = 0; j < 4; j++) {
            int col = bn + wn + j * 8 + t * 2;
            float2 bv = *reinterpret_cast<const float2*>(bias + col);
            float v0 = fmaxf(acc[i][j][0] + bv.x, 0.f);
            float v1 = fmaxf(acc[i][j][1] + bv.y, 0.f);
            float v2 = fmaxf(acc[i][j][2] + bv.x, 0.f);
            float v3 = fmaxf(acc[i][j][3] + bv.y, 0.f);
            size_t i0 = (size_t)orow0 * 512 + col;
            size_t i1 = (size_t)orow1 * 512 + col;
            *reinterpret_cast<uint32_t*>(Xh + i0) = pack_bf16(v0, v1);
            *reinterpret_cast<uint32_t*>(Xl + i0) =
                pack_bf16(v0 - bf16_hi_f(v0), v1 - bf16_hi_f(v1));
            *reinterpret_cast<uint32_t*>(Xh + i1) = pack_bf16(v2, v3);
            *reinterpret_cast<uint32_t*>(Xl + i1) =
                pack_bf16(v2 - bf16_hi_f(v2), v3 - bf16_hi_f(v3));
        }
    }
}

// ---------------------------------------------------------------------------
// Fused projections: z selects problem (K=512), plane output.
// ---------------------------------------------------------------------------
struct QKVArgs {
    const __nv_bfloat16* Ah[4];
    const __nv_bfloat16* Al[4];
    const __nv_bfloat16* Bh[4];
    const __nv_bfloat16* Bl[4];
    const float* bias[4];
    __nv_bfloat16* Ch[4];
    __nv_bfloat16* Cl[4];
};
__global__ __launch_bounds__(256, 2)
void gemm_qkv_kernel(QKVArgs args)
{
    extern __shared__ __align__(16) char dsm[];
    const int K = 512;
    int z = blockIdx.z;
    const __nv_bfloat16* Ah = args.Ah[z];
    const __nv_bfloat16* Al = args.Al[z];
    const __nv_bfloat16* Bthi = args.Bh[z];
    const __nv_bfloat16* Btlo = args.Bl[z];
    const float* bias = args.bias[z];
    __nv_bfloat16* Chi = args.Ch[z];
    __nv_bfloat16* Clo = args.Cl[z];

    int tid = threadIdx.x;
    int wid = tid >> 5, lane = tid & 31;
    int g = lane >> 2, t = lane & 3;
    int bm = blockIdx.y * 128, bn = blockIdx.x * 128;
    int wm = (wid & 1) * 64, wn = (wid >> 1) * 32;
    const int NC = 16;
    int lm = lane & 15, kq = (lane >> 4) << 3;
    int nb = (lane & 7) + ((lane >> 4) << 3);
    int kb2 = ((lane >> 3) & 1) * 8;

    int fr[2], fc[2];
#pragma unroll
    for (int i = 0; i < 2; i++) { int f = tid + i * 256; fr[i] = f >> 2; fc[i] = (f & 3) * 8; }

    float acc[4][4][4];
#pragma unroll
    for (int i = 0; i < 4; i++)
#pragma unroll
        for (int j = 0; j < 4; j++)
#pragma unroll
            for (int r = 0; r < 4; r++) acc[i][j][r] = 0.f;

    auto load_stage = [&](uint32_t st, int k0) {
#pragma unroll
        for (int i = 0; i < 2; i++) {
            uint32_t doff = (uint32_t)(fr[i] * RSTR + fc[i]) * 2;
            size_t ga = (size_t)(bm + fr[i]) * K + k0 + fc[i];
            size_t gb = (size_t)(bn + fr[i]) * K + k0 + fc[i];
            CPA16(st + doff, Ah + ga);
            CPA16(st + PLANE_B + doff, Al + ga);
            CPA16(st + 2 * PLANE_B + doff, Bthi + gb);
            CPA16(st + 3 * PLANE_B + doff, Btlo + gb);
        }
        CPA_COMMIT();
    };

    load_stage(smaddr(dsm), 0);
    CPA_WAIT(0);
    __syncthreads();

    for (int chunk = 0; chunk < NC; chunk++) {
        uint32_t cur = smaddr(dsm) + (chunk & 1) * STAGE_B;
        bool more = (chunk + 1 < NC);
        if (more)
            load_stage(smaddr(dsm) + ((chunk + 1) & 1) * STAGE_B, (chunk + 1) << 5);
        gemm_chunk_pipe(cur, acc, wm, wn, lm, kq, nb, kb2, more);
    }

#pragma unroll
    for (int i = 0; i < 4; i++) {
        int row0 = bm + wm + i * 16 + g;
#pragma unroll
        for (int j = 0; j < 4; j++) {
            int col = bn + wn + j * 8 + t * 2;
            float2 bv = *reinterpret_cast<const float2*>(bias + col);
            float v0 = acc[i][j][0] + bv.x, v1 = acc[i][j][1] + bv.y;
            float v2 = acc[i][j][2] + bv.x, v3 = acc[i][j][3] + bv.y;
            size_t i0 = (size_t)row0 * 512 + col;
            size_t i1 = (size_t)(row0 + 8) * 512 + col;
            *reinterpret_cast<uint32_t*>(Chi + i0) = pack_bf16(v0, v1);
            *reinterpret_cast<uint32_t*>(Clo + i0) =
                pack_bf16(v0 - bf16_hi_f(v0), v1 - bf16_hi_f(v1));
            *reinterpret_cast<uint32_t*>(Chi + i1) = pack_bf16(v2, v3);
            *reinterpret_cast<uint32_t*>(Clo + i1) =
                pack_bf16(v2 - bf16_hi_f(v2), v3 - bf16_hi_f(v3));
        }
    }
}

// ---------------------------------------------------------------------------
// Flash attention: per-q-tile CTAs, heavy-first (qt = 3 - bx).
// cp.async double-buffered K/V, Q frags in registers.
// OUT=0: write f32 Op + planes. OUT=1: Op += relu(result).
// ---------------------------------------------------------------------------
#define QS 72
#define FPL (64 * QS)
#define FSTG_B (4 * FPL * 2)
#define FL_SMEM (2 * FSTG_B)

template<int OUT>
__global__ __launch_bounds__(256, 2) void flash_bf16_kernel(
    const __nv_bfloat16* __restrict__ Qh, const __nv_bfloat16* __restrict__ Ql,
    const __nv_bfloat16* __restrict__ Kh, const __nv_bfloat16* __restrict__ Kl,
    const __nv_bfloat16* __restrict__ Vh, const __nv_bfloat16* __restrict__ Vl,
    float* __restrict__ Op,
    __nv_bfloat16* __restrict__ Ohp, __nv_bfloat16* __restrict__ Olp)
{
    extern __shared__ __align__(16) char fsm[];

    int tid = threadIdx.x;
    int wid = tid >> 5, lane = tid & 31;
    int g = lane >> 2, t = lane & 3;
    int qt = 3 - (int)blockIdx.x;                 // heavy CTAs scheduled first
    int h = blockIdx.y, b = blockIdx.z;
    size_t kvoff = ((size_t)b * SEQ) * EMB + h * DHD;
    size_t qoff = ((size_t)(b * SEQ + qt * 128)) * EMB + h * DHD;

    int rb = wid * 16;
    int lm = lane & 15, kq = (lane >> 4) << 3;
    int nbk = (lane & 7) + ((lane >> 4) << 3);
    int kb2 = ((lane >> 3) & 1) * 8;
    int kv = (lane & 7) + ((lane >> 3) & 1) * 8;
    int nv = (lane >> 4) << 3;

    int fr[2], fc[2];
#pragma unroll
    for (int i = 0; i < 2; i++) {
        int f = tid + i * 256;
        fr[i] = f >> 3; fc[i] = (f & 7) * 8;
    }

    // ---- stage Q, hoist fragments ----
    uint32_t qah[4][4], qal[4][4];
    {
        __nv_bfloat16* sQh = reinterpret_cast<__nv_bfloat16*>(fsm);
        __nv_bfloat16* sQl = sQh + 128 * QS;
#pragma unroll
        for (int i = 0; i < 4; i++) {
            int f = tid + i * 256;
            int r = f >> 3, c = (f & 7) * 8;
            *reinterpret_cast<uint4*>(sQh + r * QS + c) =
                *reinterpret_cast<const uint4*>(Qh + qoff + (size_t)r * EMB + c);
            *reinterpret_cast<uint4*>(sQl + r * QS + c) =
                *reinterpret_cast<const uint4*>(Ql + qoff + (size_t)r * EMB + c);
        }
        __syncthreads();
        uint32_t uQh = smaddr(sQh), uQl = smaddr(sQl);
#pragma unroll
        for (int kk = 0; kk < 4; kk++) {
            uint32_t qo = (uint32_t)((rb + lm) * QS + kk * 16 + kq) * 2;
            ldm_x4(qah[kk], uQh + qo);
            ldm_x4(qal[kk], uQl + qo);
        }
        __syncthreads();
    }

    int ktmax = qt * 2 + 1;
    int wmaxrow = qt * 128 + rb + 15;
    int row0g = qt * 128 + rb + g, row1g = row0g + 8;

    {
        uint32_t st = smaddr(fsm);
#pragma unroll
        for (int i = 0; i < 2; i++) {
            uint32_t doff = (uint32_t)(fr[i] * QS + fc[i]) * 2;
            size_t go = kvoff + (size_t)fr[i] * EMB + fc[i];
            CPA16(st + doff, Kh + go);
            CPA16(st + FPL * 2 + doff, Kl + go);
            CPA16(st + 2 * FPL * 2 + doff, Vh + go);
            CPA16(st + 3 * FPL * 2 + doff, Vl + go);
        }
        CPA_COMMIT();
    }

    float m0 = -INFINITY, m1 = -INFINITY, l0 = 0.f, l1 = 0.f;
    float acc[8][4];
#pragma unroll
    for (int j = 0; j < 8; j++)
#pragma unroll
        for (int r = 0; r < 4; r++) acc[j][r] = 0.f;

    for (int kt = 0; kt <= ktmax; kt++) {
        uint32_t cur = smaddr(fsm) + (kt & 1) * FSTG_B;
        bool more = (kt < ktmax);
        if (more) {
            uint32_t nxt = smaddr(fsm) + ((kt + 1) & 1) * FSTG_B;
            size_t ko = kvoff + (size_t)(kt + 1) * 64 * EMB;
#pragma unroll
            for (int i = 0; i < 2; i++) {
                uint32_t doff = (uint32_t)(fr[i] * QS + fc[i]) * 2;
                size_t go = ko + (size_t)fr[i] * EMB + fc[i];
                CPA16(nxt + doff, Kh + go);
                CPA16(nxt + FPL * 2 + doff, Kl + go);
                CPA16(nxt + 2 * FPL * 2 + doff, Vh + go);
                CPA16(nxt + 3 * FPL * 2 + doff, Vl + go);
            }
            CPA_COMMIT();
            CPA_WAIT(1);
        } else {
            CPA_WAIT(0);
        }
        __syncthreads();

        if (kt * 64 <= wmaxrow) {
            uint32_t uKh = cur, uKl = cur + FPL * 2;
            uint32_t uVh = cur + 2 * FPL * 2, uVl = cur + 3 * FPL * 2;

            float s[8][4];
#pragma unroll
            for (int j = 0; j < 8; j++)
#pragma unroll
                for (int r = 0; r < 4; r++) s[j][r] = 0.f;
#pragma unroll
            for (int kk = 0; kk < 4; kk++) {
#pragma unroll
                for (int jp = 0; jp < 4; jp++) {
                    uint32_t koff = (uint32_t)((jp * 16 + nbk) * QS + kk * 16 + kb2) * 2;
                    uint32_t rh[4], rl[4];
                    ldm_x4(rh, uKh + koff);
                    ldm_x4(rl, uKl + koff);
                    uint32_t b0[2] = { rh[0], rh[1] }, b1[2] = { rh[2], rh[3] };
                    uint32_t c0[2] = { rl[0], rl[1] }, c1[2] = { rl[2], rl[3] };
                    mma_bf16(s[2 * jp],     qah[kk], b0);
                    mma_bf16(s[2 * jp + 1], qah[kk], b1);
                    mma_bf16(s[2 * jp],     qal[kk], b0);
                    mma_bf16(s[2 * jp + 1], qal[kk], b1);
                    mma_bf16(s[2 * jp],     qah[kk], c0);
                    mma_bf16(s[2 * jp + 1], qah[kk], c1);
                }
            }

            int colb = kt * 64 + t * 2;
#pragma unroll
            for (int j = 0; j < 8; j++) {
                int c0 = colb + j * 8, c1 = c0 + 1;
                s[j][0] = (c0 > row0g) ? -INFINITY : s[j][0] * ATTN_SCALE;
                s[j][1] = (c1 > row0g) ? -INFINITY : s[j][1] * ATTN_SCALE;
                s[j][2] = (c0 > row1g) ? -INFINITY : s[j][2] * ATTN_SCALE;
                s[j][3] = (c1 > row1g) ? -INFINITY : s[j][3] * ATTN_SCALE;
            }

            float tm0 = -INFINITY, tm1 = -INFINITY;
#pragma unroll
            for (int j = 0; j < 8; j++) {
                tm0 = fmaxf(tm0, fmaxf(s[j][0], s[j][1]));
                tm1 = fmaxf(tm1, fmaxf(s[j][2], s[j][3]));
            }
            tm0 = fmaxf(tm0, __shfl_xor_sync(0xFFFFFFFFu, tm0, 1));
            tm0 = fmaxf(tm0, __shfl_xor_sync(0xFFFFFFFFu, tm0, 2));
            tm1 = fmaxf(tm1, __shfl_xor_sync(0xFFFFFFFFu, tm1, 1));
            tm1 = fmaxf(tm1, __shfl_xor_sync(0xFFFFFFFFu, tm1, 2));
            float m0n = fmaxf(m0, tm0), m1n = fmaxf(m1, tm1);
            float ms0 = fmaxf(m0n, -1e30f), ms1 = fmaxf(m1n, -1e30f);
            float alpha0 = __expf(m0 - ms0), alpha1 = __expf(m1 - ms1);
            m0 = m0n; m1 = m1n;
#pragma unroll
            for (int j = 0; j < 8; j++) {
                acc[j][0] *= alpha0; acc[j][1] *= alpha0;
                acc[j][2] *= alpha1; acc[j][3] *= alpha1;
            }

            float ps0 = 0.f, ps1 = 0.f;
#pragma unroll
            for (int kk = 0; kk < 4; kk++) {
                int j0 = 2 * kk, j1 = 2 * kk + 1;
                float p00 = __expf(s[j0][0] - ms0), p01 = __expf(s[j0][1] - ms0);
                float p02 = __expf(s[j0][2] - ms1), p03 = __expf(s[j0][3] - ms1);
                float p10 = __expf(s[j1][0] - ms0), p11 = __expf(s[j1][1] - ms0);
                float p12 = __expf(s[j1][2] - ms1), p13 = __expf(s[j1][3] - ms1);
                ps0 += p00 + p01 + p10 + p11;
                ps1 += p02 + p03 + p12 + p13;
                uint32_t pah[4], pal[4];
                pah[0] = pack_bf16(p00, p01);
                pah[1] = pack_bf16(p02, p03);
                pah[2] = pack_bf16(p10, p11);
                pah[3] = pack_bf16(p12, p13);
                pal[0] = pack_bf16(p00 - bf16_hi_f(p00), p01 - bf16_hi_f(p01));
                pal[1] = pack_bf16(p02 - bf16_hi_f(p02), p03 - bf16_hi_f(p03));
                pal[2] = pack_bf16(p10 - bf16_hi_f(p10), p11 - bf16_hi_f(p11));
                pal[3] = pack_bf16(p12 - bf16_hi_f(p12), p13 - bf16_hi_f(p13));
#pragma unroll
                for (int jdp = 0; jdp < 4; jdp++) {
                    uint32_t voff = (uint32_t)((kk * 16 + kv) * QS + jdp * 16 + nv) * 2;
                    uint32_t rh[4], rl[4];
                    ldm_x4t(rh, uVh + voff);
                    ldm_x4t(rl, uVl + voff);
                    uint32_t b0[2] = { rh[0], rh[1] }, b1[2] = { rh[2], rh[3] };
                    uint32_t c0[2] = { rl[0], rl[1] }, c1[2] = { rl[2], rl[3] };
                    mma_bf16(acc[2 * jdp],     pah, b0);
                    mma_bf16(acc[2 * jdp + 1], pah, b1);
                    mma_bf16(acc[2 * jdp],     pal, b0);
                    mma_bf16(acc[2 * jdp + 1], pal, b1);
                    mma_bf16(acc[2 * jdp],     pah, c0);
                    mma_bf16(acc[2 * jdp + 1], pah, c1);
                }
            }
            ps0 += __shfl_xor_sync(0xFFFFFFFFu, ps0, 1);
            ps0 += __shfl_xor_sync(0xFFFFFFFFu, ps0, 2);
            ps1 += __shfl_xor_sync(0xFFFFFFFFu, ps1, 1);
            ps1 += __shfl_xor_sync(0xFFFFFFFFu, ps1, 2);
            l0 = l0 * alpha0 + ps0;
            l1 = l1 * alpha1 + ps1;
        }
        __syncthreads();
    }

    float inv0 = 1.f / l0, inv1 = 1.f / l1;
#pragma unroll
    for (int jd = 0; jd < 8; jd++) {
        int c = jd * 8 + t * 2;
        size_t i0 = qoff + (size_t)(rb + g) * EMB + c;
        size_t i1 = qoff + (size_t)(rb + g + 8) * EMB + c;
        float o00 = acc[jd][0] * inv0, o01 = acc[jd][1] * inv0;
        float o10 = acc[jd][2] * inv1, o11 = acc[jd][3] * inv1;
        if (OUT == 0) {
            *reinterpret_cast<float2*>(Op + i0) = make_float2(o00, o01);
            *reinterpret_cast<float2*>(Op + i1) = make_float2(o10, o11);
            *reinterpret_cast<uint32_t*>(Ohp + i0) = pack_bf16(o00, o01);
            *reinterpret_cast<uint32_t*>(Olp + i0) =
                pack_bf16(o00 - bf16_hi_f(o00), o01 - bf16_hi_f(o01));
            *reinterpret_cast<uint32_t*>(Ohp + i1) = pack_bf16(o10, o11);
            *reinterpret_cast<uint32_t*>(Olp + i1) =
                pack_bf16(o10 - bf16_hi_f(o10), o11 - bf16_hi_f(o11));
        } else {
            float2 e0 = *reinterpret_cast<float2*>(Op + i0);
            float2 e1 = *reinterpret_cast<float2*>(Op + i1);
            *reinterpret_cast<float2*>(Op + i0) =
                make_float2(e0.x + fmaxf(o00, 0.f), e0.y + fmaxf(o01, 0.f));
            *reinterpret_cast<float2*>(Op + i1) =
                make_float2(e1.x + fmaxf(o10, 0.f), e1.y + fmaxf(o11, 0.f));
        }
    }
}

// ---------------------------------------------------------------------------
__global__ __launch_bounds__(256) void out_proj_kernel(
    const float* __restrict__ out, const float* __restrict__ Wout,
    const float* __restrict__ bout, float* __restrict__ y)
{
    int g = blockIdx.x * 8 + (threadIdx.x >> 5);
    int lane = threadIdx.x & 31;
    const float4* o4 = reinterpret_cast<const float4*>(out + (size_t)g * EMB);
    const float4* w4 = reinterpret_cast<const float4*>(Wout);
    float s = 0.f;
#pragma unroll
    for (int i = 0; i < 4; i++) {
        float4 a = o4[lane + 32 * i];
        float4 b = w4[lane + 32 * i];
        s += a.x * b.x + a.y * b.y + a.z * b.z + a.w * b.w;
    }
#pragma unroll
    for (int off = 16; off > 0; off >>= 1)
        s += __shfl_xor_sync(0xFFFFFFFFu, s, off);
    if (lane == 0) y[g] = s + bout[0];
}

// ---------------------------------------------------------------------------
extern "C" void kernel_launch(void* const* d_in, const int* in_sizes, int n_in,
                              void* d_out, int out_size)
{
    const int*   item_inputs  = (const int*)d_in[0];
    const int*   skill_inputs = (const int*)d_in[1];
    const int*   label_inputs = (const int*)d_in[2];
    const int*   item_ids     = (const int*)d_in[3];
    const int*   skill_ids    = (const int*)d_in[4];
    const float* item_emb     = (const float*)d_in[5];
    const float* skill_emb    = (const float*)d_in[6];
    const float* W_in         = (const float*)d_in[7];
    const float* b_in         = (const float*)d_in[8];
    const float* Wq           = (const float*)d_in[9];
    const float* bq           = (const float*)d_in[10];
    const float* Wk           = (const float*)d_in[11];
    const float* bk           = (const float*)d_in[12];
    const float* Wv           = (const float*)d_in[13];
    const float* bv           = (const float*)d_in[14];
    const float* W_out        = (const float*)d_in[22];
    const float* b_out        = (const float*)d_in[23];
    float* y = (float*)d_out;

    float* outb;
    __nv_bfloat16 *w, *hh, *hl, *qrh, *qrl, *xh, *xl, *oh, *ol;
    __nv_bfloat16 *q1h, *q1l, *q2h, *q2l, *kh, *kl, *vh, *vl;
    int *perm, *n1;
    cudaGetSymbolAddress((void**)&outb, g_outb);
    cudaGetSymbolAddress((void**)&w,    g_W);
    cudaGetSymbolAddress((void**)&hh,   g_Hh);
    cudaGetSymbolAddress((void**)&hl,   g_Hl);
    cudaGetSymbolAddress((void**)&qrh,  g_QRh);
    cudaGetSymbolAddress((void**)&qrl,  g_QRl);
    cudaGetSymbolAddress((void**)&xh,   g_Xh);
    cudaGetSymbolAddress((void**)&xl,   g_Xl);
    cudaGetSymbolAddress((void**)&oh,   g_Oh);
    cudaGetSymbolAddress((void**)&ol,   g_Ol);
    cudaGetSymbolAddress((void**)&q1h,  g_Q1h);
    cudaGetSymbolAddress((void**)&q1l,  g_Q1l);
    cudaGetSymbolAddress((void**)&q2h,  g_Q2h);
    cudaGetSymbolAddress((void**)&q2l,  g_Q2l);
    cudaGetSymbolAddress((void**)&kh,   g_Kh);
    cudaGetSymbolAddress((void**)&kl,   g_Kl);
    cudaGetSymbolAddress((void**)&vh,   g_Vh);
    cudaGetSymbolAddress((void**)&vl,   g_Vl);
    cudaGetSymbolAddress((void**)&perm, g_perm);
    cudaGetSymbolAddress((void**)&n1,   g_n1);

    cudaFuncSetAttribute(flash_bf16_kernel<0>,
                         cudaFuncAttributeMaxDynamicSharedMemorySize, FL_SMEM);
    cudaFuncSetAttribute(flash_bf16_kernel<1>,
                         cudaFuncAttributeMaxDynamicSharedMemorySize, FL_SMEM);
    cudaFuncSetAttribute(gemm_mlp_kernel,
                         cudaFuncAttributeMaxDynamicSharedMemorySize, GEMM_SMEM);
    cudaFuncSetAttribute(gemm_qkv_kernel,
                         cudaFuncAttributeMaxDynamicSharedMemorySize, GEMM_SMEM);

    __nv_bfloat16* win_hi = w;
    __nv_bfloat16* win_lo = w + 512 * 1024;
    __nv_bfloat16* qkv_hi[2][3];
    __nv_bfloat16* qkv_lo[2][3];
    {
        __nv_bfloat16* p = w + 2 * 512 * 1024;
        for (int l = 0; l < 2; l++)
            for (int m = 0; m < 3; m++) {
                qkv_hi[l][m] = p; p += 512 * 512;
                qkv_lo[l][m] = p; p += 512 * 512;
            }
    }

    // ---- stream fork (graph-capturable; host objects leak, no device alloc) --
    cudaStream_t s2;
    cudaStreamCreateWithFlags(&s2, cudaStreamNonBlocking);
    cudaEvent_t e0, eG, eT, eQ;
    cudaEventCreateWithFlags(&e0, cudaEventDisableTiming);
    cudaEventCreateWithFlags(&eG, cudaEventDisableTiming);
    cudaEventCreateWithFlags(&eT, cudaEventDisableTiming);
    cudaEventCreateWithFlags(&eQ, cudaEventDisableTiming);

    cudaEventRecord(e0, 0);
    cudaStreamWaitEvent(s2, e0, 0);

    // s2 branch: partition -> transposes
    partition_kernel<<<1, 512, 0, s2>>>(label_inputs, perm, n1);
    {
        TrAll ta;
        ta.src[0] = W_in; ta.dhi[0] = win_hi; ta.dlo[0] = win_lo; ta.K[0] = 1024; ta.yoff[0] = 0;
        ta.src[1] = W_in; ta.dhi[1] = win_hi; ta.dlo[1] = win_lo; ta.K[1] = 1024; ta.yoff[1] = 16;
        const float* srcs[3] = { Wq, Wk, Wv };
        for (int l = 0; l < 2; l++)
            for (int m = 0; m < 3; m++) {
                int zi = 2 + l * 3 + m;
                ta.src[zi] = srcs[m] + (size_t)l * 512 * 512;
                ta.dhi[zi] = qkv_hi[l][m];
                ta.dlo[zi] = qkv_lo[l][m];
                ta.K[zi] = 512;
                ta.yoff[zi] = 0;
            }
        transpose_all_kernel<<<dim3(16, 16, 8), 256, 0, s2>>>(ta);
    }
    cudaEventRecord(eT, s2);

    // default: gather
    gather_kernel<<<TOT, 128>>>(item_inputs, skill_inputs,
                                item_ids, skill_ids, item_emb, skill_emb,
                                hh, hl, qrh, qrl);
    cudaEventRecord(eG, 0);

    // s2: Q1,Q2
    cudaStreamWaitEvent(s2, eG, 0);
    {
        QKVArgs qa;
        qa.Ah[0] = qrh; qa.Al[0] = qrl;
        qa.Ah[1] = qrh; qa.Al[1] = qrl;
        qa.Ah[2] = qrh; qa.Al[2] = qrl;
        qa.Ah[3] = qrh; qa.Al[3] = qrl;
        qa.Bh[0] = qkv_hi[0][0]; qa.Bl[0] = qkv_lo[0][0];
        qa.Bh[1] = qkv_hi[1][0]; qa.Bl[1] = qkv_lo[1][0];
        qa.Bh[2] = qkv_hi[0][0]; qa.Bl[2] = qkv_lo[0][0];
        qa.Bh[3] = qkv_hi[1][0]; qa.Bl[3] = qkv_lo[1][0];
        qa.bias[0] = bq; qa.bias[1] = bq + EMB;
        qa.bias[2] = bq; qa.bias[3] = bq + EMB;
        qa.Ch[0] = q1h; qa.Cl[0] = q1l;
        qa.Ch[1] = q2h; qa.Cl[1] = q2l;
        qa.Ch[2] = q1h; qa.Cl[2] = q1l;
        qa.Ch[3] = q2h; qa.Cl[3] = q2l;
        gemm_qkv_kernel<<<dim3(4, 128, 2), 256, GEMM_SMEM, s2>>>(qa);
    }
    cudaEventRecord(eQ, s2);

    // default: MLP
    cudaStreamWaitEvent(0, eT, 0);
    gemm_mlp_kernel<<<dim3(4, 128), 256, GEMM_SMEM>>>(
        hh, hl, win_hi, win_lo, b_in, xh, xl, perm, n1);

    // default: K1,V1
    {
        QKVArgs qa;
        qa.Ah[0] = xh; qa.Al[0] = xl;
        qa.Ah[1] = xh; qa.Al[1] = xl;
        qa.Ah[2] = xh; qa.Al[2] = xl;
        qa.Ah[3] = xh; qa.Al[3] = xl;
        qa.Bh[0] = qkv_hi[0][1]; qa.Bl[0] = qkv_lo[0][1];
        qa.Bh[1] = qkv_hi[0][2]; qa.Bl[1] = qkv_lo[0][2];
        qa.Bh[2] = qkv_hi[0][1]; qa.Bl[2] = qkv_lo[0][1];
        qa.Bh[3] = qkv_hi[0][2]; qa.Bl[3] = qkv_lo[0][2];
        qa.bias[0] = bk; qa.bias[1] = bv;
        qa.bias[2] = bk; qa.bias[3] = bv;
        qa.Ch[0] = kh; qa.Cl[0] = kl;
        qa.Ch[1] = vh; qa.Cl[1] = vl;
        qa.Ch[2] = kh; qa.Cl[2] = kl;
        qa.Ch[3] = vh; qa.Cl[3] = vl;
        gemm_qkv_kernel<<<dim3(4, 128, 2), 256, GEMM_SMEM>>>(qa);
    }

    // join: flash1 needs Q1 (s2) + K1,V1 (default); per-q-tile grid
    cudaStreamWaitEvent(0, eQ, 0);
    flash_bf16_kernel<0><<<dim3(4, NH, Bsz), 256, FL_SMEM>>>(
        q1h, q1l, kh, kl, vh, vl, outb, oh, ol);

    // K2,V2
    {
        QKVArgs qa;
        qa.Ah[0] = oh; qa.Al[0] = ol;
        qa.Ah[1] = oh; qa.Al[1] = ol;
        qa.Ah[2] = oh; qa.Al[2] = ol;
        qa.Ah[3] = oh; qa.Al[3] = ol;
        qa.Bh[0] = qkv_hi[1][1]; qa.Bl[0] = qkv_lo[1][1];
        qa.Bh[1] = qkv_hi[1][2]; qa.Bl[1] = qkv_lo[1][2];
        qa.Bh[2] = qkv_hi[1][1]; qa.Bl[2] = qkv_lo[1][1];
        qa.Bh[3] = qkv_hi[1][2]; qa.Bl[3] = qkv_lo[1][2];
        qa.bias[0] = bk + EMB; qa.bias[1] = bv + EMB;
        qa.bias[2] = bk + EMB; qa.bias[3] = bv + EMB;
        qa.Ch[0] = kh; qa.Cl[0] = kl;
        qa.Ch[1] = vh; qa.Cl[1] = vl;
        qa.Ch[2] = kh; qa.Cl[2] = kl;
        qa.Ch[3] = vh; qa.Cl[3] = vl;
        gemm_qkv_kernel<<<dim3(4, 128, 2), 256, GEMM_SMEM>>>(qa);
    }
    // flash layer 2 (residual add), per-q-tile grid
    flash_bf16_kernel<1><<<dim3(4, NH, Bsz), 256, FL_SMEM>>>(
        q2h, q2l, kh, kl, vh, vl, outb, nullptr, nullptr);
    // output projection
    out_proj_kernel<<<TOT / 8, 256>>>(outb, W_out, b_out, y);
}